// round 4
// baseline (speedup 1.0000x reference)
#include <cuda_runtime.h>
#include <cuda_fp16.h>
#include <cstdint>

#define BATCH 32768
#define NCH   256
#define FLAT  3072
#define NRED  152
#define NBLK_MOM 128
#define EPSV  1e-5f

// ---------------- device scratch (no allocations allowed) ----------------
__device__ float g_part[NBLK_MOM][NRED];
__device__ float g_wscaled[NCH * 16];
__device__ float g_shift[NCH];
// fc1 weights, layout [k'][n] fp16 split (n<64 policy, n>=64 value), k'=p*256+c
__device__ __half g_w1hi[FLAT * 128];
__device__ __half g_w1lo[FLAT * 128];

// ======================= PTX helpers (baseline sm_80+) ==================
__device__ __forceinline__ uint32_t smem_u32(const void* p) {
    uint32_t a;
    asm("{ .reg .u64 t; cvta.to.shared.u64 t, %1; cvt.u32.u64 %0, t; }"
        : "=r"(a) : "l"(p));
    return a;
}
#define CP_ASYNC16(dst, src) \
    asm volatile("cp.async.cg.shared.global [%0], [%1], 16;" \
        :: "r"(dst), "l"(src) : "memory")
#define CP_COMMIT() asm volatile("cp.async.commit_group;" ::: "memory")
#define CP_WAIT1()  asm volatile("cp.async.wait_group 1;" ::: "memory")
#define CP_WAIT0()  asm volatile("cp.async.wait_group 0;" ::: "memory")

__device__ __forceinline__ void ldsm_x4(uint32_t r[4], uint32_t addr) {
    asm volatile("ldmatrix.sync.aligned.m8n8.x4.shared.b16 {%0,%1,%2,%3}, [%4];"
        : "=r"(r[0]), "=r"(r[1]), "=r"(r[2]), "=r"(r[3]) : "r"(addr));
}
__device__ __forceinline__ void ldsm_x4t(uint32_t r[4], uint32_t addr) {
    asm volatile("ldmatrix.sync.aligned.m8n8.x4.trans.shared.b16 {%0,%1,%2,%3}, [%4];"
        : "=r"(r[0]), "=r"(r[1]), "=r"(r[2]), "=r"(r[3]) : "r"(addr));
}
__device__ __forceinline__ void mma16816(float& d0, float& d1, float& d2, float& d3,
                                         uint32_t a0, uint32_t a1, uint32_t a2, uint32_t a3,
                                         uint32_t b0, uint32_t b1) {
    asm volatile(
        "mma.sync.aligned.m16n8k16.row.col.f32.f16.f16.f32 "
        "{%0,%1,%2,%3}, {%4,%5,%6,%7}, {%8,%9}, {%0,%1,%2,%3};"
        : "+f"(d0), "+f"(d1), "+f"(d2), "+f"(d3)
        : "r"(a0), "r"(a1), "r"(a2), "r"(a3), "r"(b0), "r"(b1));
}

// =========================================================================
// K1: patch moments (proven in R1)
// =========================================================================
__global__ void k_moments(const float* __restrict__ x)
{
    int b = blockIdx.x * 256 + threadIdx.x;
    const float* xb = x + b * 42;
    float xv[42];
#pragma unroll
    for (int i = 0; i < 42; i++) xv[i] = xb[i];

    __shared__ float red[8][NRED];
    int lane = threadIdx.x & 31;
    int warp = threadIdx.x >> 5;

    int idx = 0;
#pragma unroll
    for (int k = 0; k < 16; k++) {
        float s = 0.f;
#pragma unroll
        for (int r = 0; r < 3; r++)
#pragma unroll
            for (int c = 0; c < 4; c++)
                s += xv[(r + (k >> 2)) * 7 + (c + (k & 3))];
#pragma unroll
        for (int o = 16; o; o >>= 1) s += __shfl_xor_sync(0xffffffffu, s, o);
        if (lane == 0) red[warp][idx] = s;
        idx++;
    }
#pragma unroll
    for (int k = 0; k < 16; k++) {
#pragma unroll
        for (int l = k; l < 16; l++) {
            float s = 0.f;
#pragma unroll
            for (int r = 0; r < 3; r++)
#pragma unroll
                for (int c = 0; c < 4; c++)
                    s += xv[(r + (k >> 2)) * 7 + (c + (k & 3))] *
                         xv[(r + (l >> 2)) * 7 + (c + (l & 3))];
#pragma unroll
            for (int o = 16; o; o >>= 1) s += __shfl_xor_sync(0xffffffffu, s, o);
            if (lane == 0) red[warp][idx] = s;
            idx++;
        }
    }
    __syncthreads();
    if (threadIdx.x < NRED) {
        float s = 0.f;
#pragma unroll
        for (int w = 0; w < 8; w++) s += red[w][threadIdx.x];
        g_part[blockIdx.x][threadIdx.x] = s;
    }
}

// =========================================================================
// K2: finalize BN fold (proven)
// =========================================================================
__global__ void k_finalize(const float* __restrict__ conv_w,
                           const float* __restrict__ bn_gamma,
                           const float* __restrict__ bn_beta)
{
    __shared__ float S[NRED];
    int t = threadIdx.x;
    if (t < NRED) {
        float s = 0.f;
        for (int bl = 0; bl < NBLK_MOM; bl++) s += g_part[bl][t];
        S[t] = s * (1.f / (12.f * (float)BATCH));
    }
    __syncthreads();
    if (t < NCH) {
        float w[16];
#pragma unroll
        for (int i = 0; i < 16; i++) w[i] = conv_w[t * 16 + i];
        float mraw = 0.f;
#pragma unroll
        for (int i = 0; i < 16; i++) mraw += w[i] * S[i];
        float q = 0.f;
        int idx = 16;
#pragma unroll
        for (int k = 0; k < 16; k++)
#pragma unroll
            for (int l = k; l < 16; l++) {
                float coef = (k == l) ? (w[k] * w[l]) : (2.f * w[k] * w[l]);
                q += coef * S[idx];
                idx++;
            }
        float var = q - mraw * mraw;
        float a = bn_gamma[t] * rsqrtf(var + EPSV);
#pragma unroll
        for (int i = 0; i < 16; i++) g_wscaled[t * 16 + i] = a * w[i];
        g_shift[t] = bn_beta[t] - a * mraw;
    }
}

// =========================================================================
// K_prep: W1 -> [k'][n] fp16-split.  kp = p*256+c maps to f = c*12+p.
// =========================================================================
__global__ void k_prep(const float* __restrict__ pw1, const float* __restrict__ vw1)
{
    int kp = blockIdx.x;       // 0..3071
    int n  = threadIdx.x;      // 0..127
    int p = kp >> 8, c = kp & 255;
    int f = c * 12 + p;
    float v = (n < 64) ? pw1[(size_t)f * 64 + n] : vw1[(size_t)f * 64 + (n - 64)];
    __half hi = __float2half_rn(v);
    __half lo = __float2half_rn(v - __half2float(hi));
    g_w1hi[(size_t)kp * 128 + n] = hi;
    g_w1lo[(size_t)kp * 128 + n] = lo;
}

// =========================================================================
// K4: FUSED conv + GEMM + heads.
// Per CTA: 128 boards x 128 outs, K=3072 in 96 chunks of 32.
// Chunk ch = patch p=ch>>3, channels c0=(ch&7)*32. A tile computed in-kernel
// (conv+BN+ReLU -> fp16 hi/lo, swizzled STS); B via cp.async (L2-resident).
//
// Dyn smem layout (bytes):
//   0      B buf0 (hi 8K | lo 8K)
//   16384  B buf1
//   32768  A buf0 (hi 8K | lo 8K)
//   49152  A buf1
//   65536  xs   [128][42] f32  (21504)
//   87040  wS   swizzled quads (16384)
//   103424 shiftS (1024)
//   total 104448
// Epilogue reuses: h1 f32 [128][129] at 0, h2 f32 [128][65] at 66560.
// =========================================================================
#define NCHUNK3  96
#define OFF_B    0
#define OFF_A    32768
#define OFF_XS   65536
#define OFF_WS   87040
#define OFF_SH   103424
#define SMEM_DYN 104448

__global__ __launch_bounds__(256, 2) void k_fused(
    const float* __restrict__ x,
    const float* __restrict__ pb1, const float* __restrict__ vb1,
    const float* __restrict__ pw2, const float* __restrict__ pb2,
    const float* __restrict__ pw3, const float* __restrict__ pb3,
    const float* __restrict__ vw2, const float* __restrict__ vb2,
    const float* __restrict__ vw3, const float* __restrict__ vb3,
    float* __restrict__ out)
{
    extern __shared__ char dyn_pool[];
    __shared__ float biasS[128];

    char* poolA = dyn_pool;
    const uint32_t pool_u = smem_u32(poolA);

    const int tid  = threadIdx.x;
    const int wid  = tid >> 5;
    const int lane = tid & 31;
    const int m0   = blockIdx.x * 128;
    const int wm   = wid & 3;
    const int wn   = wid >> 2;

    float* xsS    = (float*)(poolA + OFF_XS);
    float* shiftS = (float*)(poolA + OFF_SH);
    float4* wq    = (float4*)(poolA + OFF_WS);

    // ---- one-time smem fills ----
    if (tid < 64)       biasS[tid] = pb1[tid];
    else if (tid < 128) biasS[tid] = vb1[tid - 64];
    {   // x boards: 5376 floats
        const float* xg = x + (size_t)m0 * 42;
#pragma unroll
        for (int i = 0; i < 21; i++) xsS[tid + i * 256] = xg[tid + i * 256];
    }
    {   // folded conv weights, quad-swizzled: quad q of channel c at c*4 + (q ^ ((c>>4)&1))
        const float4* wg = (const float4*)g_wscaled;
#pragma unroll
        for (int i = 0; i < 4; i++) {
            int f = tid + i * 256;          // 0..1023
            int c = f >> 2, q = f & 3;
            wq[c * 4 + (q ^ ((c >> 4) & 1))] = wg[f];
        }
    }
    if (tid < 256) shiftS[tid] = g_shift[tid];

    // ---- B cp.async loader lanes ----
    const int brow = tid >> 3;             // 0..31
    const int bc0  = (tid & 7) * 2;
    const __half* gBhi = g_w1hi + (size_t)brow * 128 + bc0 * 8;
    const __half* gBlo = g_w1lo + (size_t)brow * 128 + bc0 * 8;
    const uint32_t swB = (uint32_t)(brow & 7);
    const uint32_t oB0 = (uint32_t)brow * 256 + (((bc0 + 0) ^ swB) << 4);
    const uint32_t oB1 = (uint32_t)brow * 256 + (((bc0 + 1) ^ swB) << 4);

    // ---- conv lanes: board, half-of-32-channels ----
    const int cvb = tid >> 1;              // 0..127
    const int cvh = tid & 1;
    const float* xrow = xsS + cvb * 42;
    const uint32_t swA = (uint32_t)((cvb >> 1) & 3);
    const uint32_t oA0 = (uint32_t)cvb * 64 + (((cvh * 2 + 0) ^ swA) << 4);
    const uint32_t oA1 = (uint32_t)cvb * 64 + (((cvh * 2 + 1) ^ swA) << 4);

    float d[2][8][4];
#pragma unroll
    for (int mi = 0; mi < 2; mi++)
#pragma unroll
        for (int nj = 0; nj < 8; nj++)
#pragma unroll
            for (int q = 0; q < 4; q++) d[mi][nj][q] = 0.f;

    const int a_r  = (lane & 15);
    const int a_hg = (lane >> 4);
    const int b_kl = ((lane >> 3) & 1) * 8 + (lane & 7);
    const int b_ng = (lane >> 4);

    // ---- prologue: issue B0, B1 ----
#pragma unroll
    for (int pc = 0; pc < 2; pc++) {
        const int kc = pc * 32;
        const uint32_t sb = pool_u + OFF_B + pc * 16384;
        CP_ASYNC16(sb + oB0, gBhi + (size_t)kc * 128);
        CP_ASYNC16(sb + oB1, gBhi + (size_t)kc * 128 + 8);
        CP_ASYNC16(sb + 8192 + oB0, gBlo + (size_t)kc * 128);
        CP_ASYNC16(sb + 8192 + oB1, gBlo + (size_t)kc * 128 + 8);
        CP_COMMIT();
    }

    __syncthreads();   // xs/wS/shift visible

    // ---- conv for chunk 0 into A buf0 ----
    {
        const int p = 0, c0 = 0;
        const float* xw = xrow + (p >> 2) * 7 + (p & 3);
        float xwin[16];
#pragma unroll
        for (int i = 0; i < 4; i++)
#pragma unroll
            for (int j = 0; j < 4; j++) xwin[i * 4 + j] = xw[i * 7 + j];
        uint32_t hpk[8], lpk[8];
        const int cb = c0 + cvh * 16;
#pragma unroll
        for (int u = 0; u < 8; u++) {
            float vv[2];
#pragma unroll
            for (int e = 0; e < 2; e++) {
                int c = cb + u * 2 + e;
                float acc = shiftS[c];
                int key = (c >> 4) & 1;
#pragma unroll
                for (int q = 0; q < 4; q++) {
                    float4 w4 = wq[c * 4 + (q ^ key)];
                    acc += w4.x * xwin[q * 4] + w4.y * xwin[q * 4 + 1] +
                           w4.z * xwin[q * 4 + 2] + w4.w * xwin[q * 4 + 3];
                }
                vv[e] = fmaxf(acc, 0.f);
            }
            __half h0 = __float2half_rn(vv[0]);
            __half h1v = __float2half_rn(vv[1]);
            float l0 = vv[0] - __half2float(h0);
            float l1 = vv[1] - __half2float(h1v);
            hpk[u] = ((uint32_t)__half_as_ushort(h1v) << 16) | __half_as_ushort(h0);
            lpk[u] = ((uint32_t)__half_as_ushort(__float2half_rn(l1)) << 16) |
                     __half_as_ushort(__float2half_rn(l0));
        }
        char* ab = poolA + OFF_A;   // buf0
        *(uint4*)(ab + oA0)        = make_uint4(hpk[0], hpk[1], hpk[2], hpk[3]);
        *(uint4*)(ab + oA1)        = make_uint4(hpk[4], hpk[5], hpk[6], hpk[7]);
        *(uint4*)(ab + 8192 + oA0) = make_uint4(lpk[0], lpk[1], lpk[2], lpk[3]);
        *(uint4*)(ab + 8192 + oA1) = make_uint4(lpk[4], lpk[5], lpk[6], lpk[7]);
    }

#pragma unroll 1
    for (int ch = 0; ch < NCHUNK3; ch++) {
        // ---- conv for chunk ch+1 into other A buffer ----
        if (ch + 1 < NCHUNK3) {
            const int chn = ch + 1;
            const int p = chn >> 3, c0 = (chn & 7) * 32;
            const float* xw = xrow + (p >> 2) * 7 + (p & 3);
            float xwin[16];
#pragma unroll
            for (int i = 0; i < 4; i++)
#pragma unroll
                for (int j = 0; j < 4; j++) xwin[i * 4 + j] = xw[i * 7 + j];
            uint32_t hpk[8], lpk[8];
            const int cb = c0 + cvh * 16;
#pragma unroll
            for (int u = 0; u < 8; u++) {
                float vv[2];
#pragma unroll
                for (int e = 0; e < 2; e++) {
                    int c = cb + u * 2 + e;
                    float acc = shiftS[c];
                    int key = (c >> 4) & 1;
#pragma unroll
                    for (int q = 0; q < 4; q++) {
                        float4 w4 = wq[c * 4 + (q ^ key)];
                        acc += w4.x * xwin[q * 4] + w4.y * xwin[q * 4 + 1] +
                               w4.z * xwin[q * 4 + 2] + w4.w * xwin[q * 4 + 3];
                    }
                    vv[e] = fmaxf(acc, 0.f);
                }
                __half h0 = __float2half_rn(vv[0]);
                __half h1v = __float2half_rn(vv[1]);
                float l0 = vv[0] - __half2float(h0);
                float l1 = vv[1] - __half2float(h1v);
                hpk[u] = ((uint32_t)__half_as_ushort(h1v) << 16) | __half_as_ushort(h0);
                lpk[u] = ((uint32_t)__half_as_ushort(__float2half_rn(l1)) << 16) |
                         __half_as_ushort(__float2half_rn(l0));
            }
            char* ab = poolA + OFF_A + (chn & 1) * 16384;
            *(uint4*)(ab + oA0)        = make_uint4(hpk[0], hpk[1], hpk[2], hpk[3]);
            *(uint4*)(ab + oA1)        = make_uint4(hpk[4], hpk[5], hpk[6], hpk[7]);
            *(uint4*)(ab + 8192 + oA0) = make_uint4(lpk[0], lpk[1], lpk[2], lpk[3]);
            *(uint4*)(ab + 8192 + oA1) = make_uint4(lpk[4], lpk[5], lpk[6], lpk[7]);
        }

        CP_WAIT1();
        __syncthreads();   // B[ch] ready; A[ch] (written last iter / prologue) visible

        const uint32_t sbB = pool_u + OFF_B + (ch & 1) * 16384;
        const uint32_t sbA = pool_u + OFF_A + (ch & 1) * 16384;

#pragma unroll
        for (int ks = 0; ks < 2; ks++) {
            uint32_t ahi[2][4], alo[2][4];
#pragma unroll
            for (int mi = 0; mi < 2; mi++) {
                int row = wm * 32 + mi * 16 + a_r;
                uint32_t chunk = (uint32_t)(ks * 2 + a_hg);
                uint32_t off = (uint32_t)row * 64 + ((chunk ^ ((row >> 1) & 3)) << 4);
                ldsm_x4(ahi[mi], sbA + off);
                ldsm_x4(alo[mi], sbA + 8192 + off);
            }
#pragma unroll
            for (int ng = 0; ng < 4; ng++) {
                int k = ks * 16 + b_kl;
                uint32_t ncg = (uint32_t)(wn * 8 + ng * 2 + b_ng);
                uint32_t off = (uint32_t)k * 256 + ((ncg ^ (k & 7)) << 4);
                uint32_t bhi[4], blo[4];
                ldsm_x4t(bhi, sbB + off);
                ldsm_x4t(blo, sbB + 8192 + off);
#pragma unroll
                for (int mi = 0; mi < 2; mi++) {
                    float* d0 = d[mi][ng * 2];
                    float* d1 = d[mi][ng * 2 + 1];
                    mma16816(d0[0], d0[1], d0[2], d0[3],
                             ahi[mi][0], ahi[mi][1], ahi[mi][2], ahi[mi][3],
                             bhi[0], bhi[1]);
                    mma16816(d1[0], d1[1], d1[2], d1[3],
                             ahi[mi][0], ahi[mi][1], ahi[mi][2], ahi[mi][3],
                             bhi[2], bhi[3]);
                    mma16816(d0[0], d0[1], d0[2], d0[3],
                             alo[mi][0], alo[mi][1], alo[mi][2], alo[mi][3],
                             bhi[0], bhi[1]);
                    mma16816(d1[0], d1[1], d1[2], d1[3],
                             alo[mi][0], alo[mi][1], alo[mi][2], alo[mi][3],
                             bhi[2], bhi[3]);
                    mma16816(d0[0], d0[1], d0[2], d0[3],
                             ahi[mi][0], ahi[mi][1], ahi[mi][2], ahi[mi][3],
                             blo[0], blo[1]);
                    mma16816(d1[0], d1[1], d1[2], d1[3],
                             ahi[mi][0], ahi[mi][1], ahi[mi][2], ahi[mi][3],
                             blo[2], blo[3]);
                }
            }
        }
        __syncthreads();   // MMA done: safe to overwrite A[(ch)&1] next iter and B[ch&1] below

        if (ch + 2 < NCHUNK3) {
            const int kc = (ch + 2) * 32;
            const uint32_t sb = pool_u + OFF_B + (ch & 1) * 16384;
            CP_ASYNC16(sb + oB0, gBhi + (size_t)kc * 128);
            CP_ASYNC16(sb + oB1, gBhi + (size_t)kc * 128 + 8);
            CP_ASYNC16(sb + 8192 + oB0, gBlo + (size_t)kc * 128);
            CP_ASYNC16(sb + 8192 + oB1, gBlo + (size_t)kc * 128 + 8);
        }
        CP_COMMIT();
    }

    CP_WAIT0();
    __syncthreads();

    // ---------------- epilogue ----------------
    float* h1 = (float*)poolA;              // [128][129]
    float* h2 = (float*)(poolA + 66560);    // [128][65]

    {
        int g  = lane >> 2;
        int t2 = (lane & 3) * 2;
#pragma unroll
        for (int mi = 0; mi < 2; mi++) {
#pragma unroll
            for (int nj = 0; nj < 8; nj++) {
                int m = wm * 32 + mi * 16 + g;
                int n = wn * 64 + nj * 8 + t2;
                h1[m * 129 + n]           = fmaxf(d[mi][nj][0] + biasS[n], 0.f);
                h1[m * 129 + n + 1]       = fmaxf(d[mi][nj][1] + biasS[n + 1], 0.f);
                h1[(m + 8) * 129 + n]     = fmaxf(d[mi][nj][2] + biasS[n], 0.f);
                h1[(m + 8) * 129 + n + 1] = fmaxf(d[mi][nj][3] + biasS[n + 1], 0.f);
            }
        }
    }
    __syncthreads();

    // layer2: 128 boards x 64 outs (32 policy | 32 value)
#pragma unroll 1
    for (int it = 0; it < 32; it++) {
        int idx = it * 256 + tid;
        int bd = idx >> 6, o = idx & 63;
        int oo = o & 31;
        const float* h1b  = h1 + bd * 129 + ((o < 32) ? 0 : 64);
        const float* wmat = (o < 32) ? pw2 : vw2;
        float s = (o < 32) ? pb2[oo] : vb2[oo];
#pragma unroll 8
        for (int k = 0; k < 64; k++) s += h1b[k] * wmat[k * 32 + oo];
        h2[bd * 65 + o] = fmaxf(s, 0.f);
    }
    __syncthreads();

    // layer3 + softmax / tanh
    if (tid < 128) {
        int gb = m0 + tid;
        const float* hp = h2 + tid * 65;
        float lg[7];
#pragma unroll
        for (int j = 0; j < 7; j++) {
            float s = pb3[j];
#pragma unroll
            for (int k = 0; k < 32; k++) s += hp[k] * pw3[k * 7 + j];
            lg[j] = s;
        }
        float mx = lg[0];
#pragma unroll
        for (int j = 1; j < 7; j++) mx = fmaxf(mx, lg[j]);
        float se = 0.f;
#pragma unroll
        for (int j = 0; j < 7; j++) { lg[j] = expf(lg[j] - mx); se += lg[j]; }
        float inv = 1.f / se;
#pragma unroll
        for (int j = 0; j < 7; j++) out[(size_t)gb * 7 + j] = lg[j] * inv;

        float v = vb3[0];
#pragma unroll
        for (int k = 0; k < 32; k++) v += hp[32 + k] * vw3[k];
        out[(size_t)BATCH * 7 + gb] = tanhf(v);
    }
}

// =========================================================================
extern "C" void kernel_launch(void* const* d_in, const int* in_sizes, int n_in,
                              void* d_out, int out_size)
{
    const float* x        = (const float*)d_in[0];
    const float* conv_w   = (const float*)d_in[1];
    /* conv_b (d_in[2]) cancels exactly through batch-norm — unused */
    const float* bn_gamma = (const float*)d_in[3];
    const float* bn_beta  = (const float*)d_in[4];
    const float* pw1 = (const float*)d_in[5];
    const float* pb1 = (const float*)d_in[6];
    const float* pw2 = (const float*)d_in[7];
    const float* pb2 = (const float*)d_in[8];
    const float* pw3 = (const float*)d_in[9];
    const float* pb3 = (const float*)d_in[10];
    const float* vw1 = (const float*)d_in[11];
    const float* vb1 = (const float*)d_in[12];
    const float* vw2 = (const float*)d_in[13];
    const float* vb2 = (const float*)d_in[14];
    const float* vw3 = (const float*)d_in[15];
    const float* vb3 = (const float*)d_in[16];
    float* out = (float*)d_out;

    cudaFuncSetAttribute(k_fused, cudaFuncAttributeMaxDynamicSharedMemorySize, SMEM_DYN);

    k_moments<<<NBLK_MOM, 256>>>(x);
    k_finalize<<<1, 256>>>(conv_w, bn_gamma, bn_beta);
    k_prep<<<FLAT, 128>>>(pw1, vw1);
    k_fused<<<BATCH / 128, 256, SMEM_DYN>>>(x, pb1, vb1, pw2, pb2, pw3, pb3,
                                            vw2, vb2, vw3, vb3, out);
}

// round 5
// speedup vs baseline: 1.7302x; 1.7302x over previous
#include <cuda_runtime.h>
#include <cuda_fp16.h>
#include <cstdint>

#define BATCH 32768
#define NCH   256
#define FLAT  3072
#define NRED  152
#define NBLK_MOM 128
#define EPSV  1e-5f

// ---------------- device scratch ----------------
__device__ float g_part[NBLK_MOM][NRED];
__device__ float g_wscaled[NCH * 16];
__device__ float g_shift[NCH];
// fc1 weights fp16 (hi only), layout [k'][n], k' = p*256 + c
__device__ __half g_w1hi[FLAT * 128];

// ======================= PTX helpers ==================
__device__ __forceinline__ uint32_t smem_u32(const void* p) {
    uint32_t a;
    asm("{ .reg .u64 t; cvta.to.shared.u64 t, %1; cvt.u32.u64 %0, t; }"
        : "=r"(a) : "l"(p));
    return a;
}
#define CP_ASYNC16(dst, src) \
    asm volatile("cp.async.cg.shared.global [%0], [%1], 16;" \
        :: "r"(dst), "l"(src) : "memory")
#define CP_COMMIT() asm volatile("cp.async.commit_group;" ::: "memory")
#define CP_WAIT1()  asm volatile("cp.async.wait_group 1;" ::: "memory")
#define CP_WAIT0()  asm volatile("cp.async.wait_group 0;" ::: "memory")

__device__ __forceinline__ void ldsm_x4(uint32_t r[4], uint32_t addr) {
    asm volatile("ldmatrix.sync.aligned.m8n8.x4.shared.b16 {%0,%1,%2,%3}, [%4];"
        : "=r"(r[0]), "=r"(r[1]), "=r"(r[2]), "=r"(r[3]) : "r"(addr));
}
__device__ __forceinline__ void ldsm_x4t(uint32_t r[4], uint32_t addr) {
    asm volatile("ldmatrix.sync.aligned.m8n8.x4.trans.shared.b16 {%0,%1,%2,%3}, [%4];"
        : "=r"(r[0]), "=r"(r[1]), "=r"(r[2]), "=r"(r[3]) : "r"(addr));
}
__device__ __forceinline__ void mma16816(float& d0, float& d1, float& d2, float& d3,
                                         uint32_t a0, uint32_t a1, uint32_t a2, uint32_t a3,
                                         uint32_t b0, uint32_t b1) {
    asm volatile(
        "mma.sync.aligned.m16n8k16.row.col.f32.f16.f16.f32 "
        "{%0,%1,%2,%3}, {%4,%5,%6,%7}, {%8,%9}, {%0,%1,%2,%3};"
        : "+f"(d0), "+f"(d1), "+f"(d2), "+f"(d3)
        : "r"(a0), "r"(a1), "r"(a2), "r"(a3), "r"(b0), "r"(b1));
}
__device__ __forceinline__ uint32_t pack_h2(float a, float b) {
    __half ha = __float2half_rn(a), hb = __float2half_rn(b);
    return ((uint32_t)__half_as_ushort(hb) << 16) | __half_as_ushort(ha);
}

// =========================================================================
// K1: patch moments (proven)
// =========================================================================
__global__ void k_moments(const float* __restrict__ x)
{
    int b = blockIdx.x * 256 + threadIdx.x;
    const float* xb = x + b * 42;
    float xv[42];
#pragma unroll
    for (int i = 0; i < 42; i++) xv[i] = xb[i];

    __shared__ float red[8][NRED];
    int lane = threadIdx.x & 31;
    int warp = threadIdx.x >> 5;

    int idx = 0;
#pragma unroll
    for (int k = 0; k < 16; k++) {
        float s = 0.f;
#pragma unroll
        for (int r = 0; r < 3; r++)
#pragma unroll
            for (int c = 0; c < 4; c++)
                s += xv[(r + (k >> 2)) * 7 + (c + (k & 3))];
#pragma unroll
        for (int o = 16; o; o >>= 1) s += __shfl_xor_sync(0xffffffffu, s, o);
        if (lane == 0) red[warp][idx] = s;
        idx++;
    }
#pragma unroll
    for (int k = 0; k < 16; k++) {
#pragma unroll
        for (int l = k; l < 16; l++) {
            float s = 0.f;
#pragma unroll
            for (int r = 0; r < 3; r++)
#pragma unroll
                for (int c = 0; c < 4; c++)
                    s += xv[(r + (k >> 2)) * 7 + (c + (k & 3))] *
                         xv[(r + (l >> 2)) * 7 + (c + (l & 3))];
#pragma unroll
            for (int o = 16; o; o >>= 1) s += __shfl_xor_sync(0xffffffffu, s, o);
            if (lane == 0) red[warp][idx] = s;
            idx++;
        }
    }
    __syncthreads();
    if (threadIdx.x < NRED) {
        float s = 0.f;
#pragma unroll
        for (int w = 0; w < 8; w++) s += red[w][threadIdx.x];
        g_part[blockIdx.x][threadIdx.x] = s;
    }
}

// =========================================================================
// K2: finalize BN fold (proven)
// =========================================================================
__global__ void k_finalize(const float* __restrict__ conv_w,
                           const float* __restrict__ bn_gamma,
                           const float* __restrict__ bn_beta)
{
    __shared__ float S[NRED];
    int t = threadIdx.x;
    if (t < NRED) {
        float s = 0.f;
        for (int bl = 0; bl < NBLK_MOM; bl++) s += g_part[bl][t];
        S[t] = s * (1.f / (12.f * (float)BATCH));
    }
    __syncthreads();
    if (t < NCH) {
        float w[16];
#pragma unroll
        for (int i = 0; i < 16; i++) w[i] = conv_w[t * 16 + i];
        float mraw = 0.f;
#pragma unroll
        for (int i = 0; i < 16; i++) mraw += w[i] * S[i];
        float q = 0.f;
        int idx = 16;
#pragma unroll
        for (int k = 0; k < 16; k++)
#pragma unroll
            for (int l = k; l < 16; l++) {
                float coef = (k == l) ? (w[k] * w[l]) : (2.f * w[k] * w[l]);
                q += coef * S[idx];
                idx++;
            }
        float var = q - mraw * mraw;
        float a = bn_gamma[t] * rsqrtf(var + EPSV);
#pragma unroll
        for (int i = 0; i < 16; i++) g_wscaled[t * 16 + i] = a * w[i];
        g_shift[t] = bn_beta[t] - a * mraw;
    }
}

// =========================================================================
// K_prep: W1 -> [k'][n] fp16 (hi only).  kp = p*256+c, f = c*12+p.
// =========================================================================
__global__ void k_prep(const float* __restrict__ pw1, const float* __restrict__ vw1)
{
    int kp = blockIdx.x;
    int n  = threadIdx.x;
    int p = kp >> 8, c = kp & 255;
    int f = c * 12 + p;
    float v = (n < 64) ? pw1[(size_t)f * 64 + n] : vw1[(size_t)f * 64 + (n - 64)];
    g_w1hi[(size_t)kp * 128 + n] = __float2half_rn(v);
}

// =========================================================================
// K4: FULLY-TENSOR fused kernel.
// Per chunk (patch p=ch>>3, channels c0=(ch&7)*32):
//   conv: A[128x32] = relu(Xp[128x16] @ Wc[16x32] + shift)  via 12 HMMA/warp
//   fc1 : D += (Ahi + Alo) @ Bhi[32x128]                    via 64 HMMA/warp
// Smem (dyn):
//   0      B bufs   2 x 8192
//   16384  A bufs   2 x (hi 8192 | lo 8192)
//   49152  Xp hi 6144 (row stride 48B) | lo 6144
//   61440  Wc hi 8192 ([16][256] halfs, swizzled) | lo 8192
//   77824  xs [128][42] f32 (21504)
//   99328  shift (1024)            total 100352
// Epilogue reuses pool: h1 [128][129] f32 @0, h2 [128][65] f32 @66560.
// =========================================================================
#define NCHUNKS  96
#define OFF_B    0
#define OFF_A    16384
#define OFF_XP   49152
#define OFF_XPL  55296
#define OFF_WC   61440
#define OFF_WCL  69632
#define OFF_XS   77824
#define OFF_SH   99328
#define SMEM_DYN 100352

__global__ __launch_bounds__(256, 2) void k_fused(
    const float* __restrict__ x,
    const float* __restrict__ pb1, const float* __restrict__ vb1,
    const float* __restrict__ pw2, const float* __restrict__ pb2,
    const float* __restrict__ pw3, const float* __restrict__ pb3,
    const float* __restrict__ vw2, const float* __restrict__ vb2,
    const float* __restrict__ vw3, const float* __restrict__ vb3,
    float* __restrict__ out)
{
    extern __shared__ char dyn_pool[];
    __shared__ float biasS[128];

    char* poolA = dyn_pool;
    const uint32_t pool_u = smem_u32(poolA);

    const int tid  = threadIdx.x;
    const int wid  = tid >> 5;
    const int lane = tid & 31;
    const int m0   = blockIdx.x * 128;
    const int wm   = wid & 3;      // fc1 m index
    const int wn   = wid >> 2;     // fc1 n index

    float* xsS    = (float*)(poolA + OFF_XS);
    float* shiftS = (float*)(poolA + OFF_SH);

    // ---- one-time smem fills ----
    if (tid < 64)       biasS[tid] = pb1[tid];
    else if (tid < 128) biasS[tid] = vb1[tid - 64];
    {
        const float* xg = x + (size_t)m0 * 42;
#pragma unroll
        for (int i = 0; i < 21; i++) xsS[tid + i * 256] = xg[tid + i * 256];
    }
    {   // folded conv weights -> Wc[k][c] fp16 split, swizzled rows of 512B
#pragma unroll
        for (int i = 0; i < 16; i++) {
            int idx = tid + i * 256;          // 0..4095
            int k = idx >> 8, c = idx & 255;
            float v = g_wscaled[c * 16 + k];
            __half h = __float2half_rn(v);
            float l = v - __half2float(h);
            uint32_t o = (uint32_t)k * 512 + ((((uint32_t)(c >> 3)) ^ (k & 7)) << 4) + (c & 7) * 2;
            *(__half*)(poolA + OFF_WC + o)  = h;
            *(__half*)(poolA + OFF_WCL + o) = __float2half_rn(l);
        }
    }
    shiftS[tid] = g_shift[tid];

    // ---- fc1 B loader lanes ----
    const int brow = tid >> 3;
    const int bc0  = (tid & 7) * 2;
    const __half* gBhi = g_w1hi + (size_t)brow * 128 + bc0 * 8;
    const uint32_t swB = (uint32_t)(brow & 7);
    const uint32_t oB0 = (uint32_t)brow * 256 + (((bc0 + 0) ^ swB) << 4);
    const uint32_t oB1 = (uint32_t)brow * 256 + (((bc0 + 1) ^ swB) << 4);

    // ---- prologue B0, B1 ----
#pragma unroll
    for (int pc = 0; pc < 2; pc++) {
        const int kc = pc * 32;
        const uint32_t sb = pool_u + OFF_B + pc * 8192;
        CP_ASYNC16(sb + oB0, gBhi + (size_t)kc * 128);
        CP_ASYNC16(sb + oB1, gBhi + (size_t)kc * 128 + 8);
        CP_COMMIT();
    }

    // ---- lane constants ----
    const int a_r  = (lane & 15);
    const int a_hg = (lane >> 4);
    const int b_kl = ((lane >> 3) & 1) * 8 + (lane & 7);
    const int b_ng = (lane >> 4);
    const int dg   = lane >> 2;            // d-frag row
    const int t2   = (lane & 3) * 2;       // d-frag col pair

    float d[2][8][4];
#pragma unroll
    for (int mi = 0; mi < 2; mi++)
#pragma unroll
        for (int nj = 0; nj < 8; nj++)
#pragma unroll
            for (int q = 0; q < 4; q++) d[mi][nj][q] = 0.f;

    __syncthreads();   // xs / Wc / shift visible

    // ================= Xp build helper (as macro-ish lambda) =============
    auto build_xp = [&](int p) {
        int row = tid >> 1;
        int chk = tid & 1;
        const float* xw = xsS + row * 42 + (p >> 2) * 7 + (p & 3);
        uint32_t hp[4], lp[4];
#pragma unroll
        for (int j = 0; j < 4; j++) {
            int k0 = chk * 8 + j * 2, k1 = k0 + 1;
            float v0 = xw[(k0 >> 2) * 7 + (k0 & 3)];
            float v1 = xw[(k1 >> 2) * 7 + (k1 & 3)];
            __half h0 = __float2half_rn(v0), h1 = __float2half_rn(v1);
            hp[j] = ((uint32_t)__half_as_ushort(h1) << 16) | __half_as_ushort(h0);
            lp[j] = pack_h2(v0 - __half2float(h0), v1 - __half2float(h1));
        }
        uint32_t o = (uint32_t)row * 48 + chk * 16;
        *(uint4*)(poolA + OFF_XP + o)  = make_uint4(hp[0], hp[1], hp[2], hp[3]);
        *(uint4*)(poolA + OFF_XPL + o) = make_uint4(lp[0], lp[1], lp[2], lp[3]);
    };

    // ================= conv chunk helper ==================================
    auto conv_chunk = [&](int chn) {
        const int c0 = (chn & 7) * 32;
        const int bg = (chn & 7) * 4;
        char* abuf = poolA + OFF_A + (chn & 1) * 16384;

        uint32_t xaddr = pool_u + OFF_XP + (uint32_t)(wid * 16 + a_r) * 48 + a_hg * 16;
        uint32_t xhi[4], xlo[4];
        ldsm_x4(xhi, xaddr);
        ldsm_x4(xlo, xaddr + 6144);

        float cd[4][4];
#pragma unroll
        for (int nt = 0; nt < 4; nt++)
#pragma unroll
            for (int q = 0; q < 4; q++) cd[nt][q] = 0.f;

#pragma unroll
        for (int nt2 = 0; nt2 < 2; nt2++) {
            uint32_t woff = (uint32_t)b_kl * 512 +
                            ((((uint32_t)(bg + nt2 * 2 + b_ng)) ^ (b_kl & 7)) << 4);
            uint32_t whi[4], wlo[4];
            ldsm_x4t(whi, pool_u + OFF_WC + woff);
            ldsm_x4t(wlo, pool_u + OFF_WCL + woff);
#pragma unroll
            for (int sub = 0; sub < 2; sub++) {
                float* cdn = cd[nt2 * 2 + sub];
                mma16816(cdn[0], cdn[1], cdn[2], cdn[3],
                         xhi[0], xhi[1], xhi[2], xhi[3], whi[2 * sub], whi[2 * sub + 1]);
                mma16816(cdn[0], cdn[1], cdn[2], cdn[3],
                         xlo[0], xlo[1], xlo[2], xlo[3], whi[2 * sub], whi[2 * sub + 1]);
                mma16816(cdn[0], cdn[1], cdn[2], cdn[3],
                         xhi[0], xhi[1], xhi[2], xhi[3], wlo[2 * sub], wlo[2 * sub + 1]);
            }
        }

        // repack: shift + ReLU + fp16 hi/lo split -> swizzled A tile
        const int r0 = wid * 16 + dg;
        const int r1 = r0 + 8;
        const uint32_t k0 = ((uint32_t)(r0 >> 1) & 3);
        const uint32_t k1 = ((uint32_t)(r1 >> 1) & 3);
#pragma unroll
        for (int nt = 0; nt < 4; nt++) {
            float2 sv = *(const float2*)&shiftS[c0 + nt * 8 + t2];
            float v00 = fmaxf(cd[nt][0] + sv.x, 0.f);
            float v01 = fmaxf(cd[nt][1] + sv.y, 0.f);
            float v10 = fmaxf(cd[nt][2] + sv.x, 0.f);
            float v11 = fmaxf(cd[nt][3] + sv.y, 0.f);
            __half h00 = __float2half_rn(v00), h01 = __float2half_rn(v01);
            __half h10 = __float2half_rn(v10), h11 = __float2half_rn(v11);
            uint32_t hi0 = ((uint32_t)__half_as_ushort(h01) << 16) | __half_as_ushort(h00);
            uint32_t hi1 = ((uint32_t)__half_as_ushort(h11) << 16) | __half_as_ushort(h10);
            uint32_t lo0 = pack_h2(v00 - __half2float(h00), v01 - __half2float(h01));
            uint32_t lo1 = pack_h2(v10 - __half2float(h10), v11 - __half2float(h11));
            uint32_t o0 = (uint32_t)r0 * 64 + (((uint32_t)nt ^ k0) << 4) + (lane & 3) * 4;
            uint32_t o1 = (uint32_t)r1 * 64 + (((uint32_t)nt ^ k1) << 4) + (lane & 3) * 4;
            *(uint32_t*)(abuf + o0)        = hi0;
            *(uint32_t*)(abuf + 8192 + o0) = lo0;
            *(uint32_t*)(abuf + o1)        = hi1;
            *(uint32_t*)(abuf + 8192 + o1) = lo1;
        }
    };

    // ---- prologue: Xp(0), conv chunk 0 ----
    build_xp(0);
    __syncthreads();
    conv_chunk(0);

    // ================= main loop =================
#pragma unroll 1
    for (int ch = 0; ch < NCHUNKS; ch++) {
        if (ch + 1 < NCHUNKS) {
            if (((ch + 1) & 7) == 0) {
                build_xp((ch + 1) >> 3);
                __syncthreads();
            }
            conv_chunk(ch + 1);
        }

        CP_WAIT1();
        __syncthreads();   // B[ch] ready; A[ch] (prev iter) visible

        const uint32_t sbB = pool_u + OFF_B + (ch & 1) * 8192;
        const uint32_t sbA = pool_u + OFF_A + (ch & 1) * 16384;

#pragma unroll
        for (int ks = 0; ks < 2; ks++) {
            uint32_t ahi[2][4], alo[2][4];
#pragma unroll
            for (int mi = 0; mi < 2; mi++) {
                int row = wm * 32 + mi * 16 + a_r;
                uint32_t chunk = (uint32_t)(ks * 2 + a_hg);
                uint32_t off = (uint32_t)row * 64 + ((chunk ^ ((row >> 1) & 3)) << 4);
                ldsm_x4(ahi[mi], sbA + off);
                ldsm_x4(alo[mi], sbA + 8192 + off);
            }
#pragma unroll
            for (int ng = 0; ng < 4; ng++) {
                int k = ks * 16 + b_kl;
                uint32_t ncg = (uint32_t)(wn * 8 + ng * 2 + b_ng);
                uint32_t off = (uint32_t)k * 256 + ((ncg ^ (k & 7)) << 4);
                uint32_t bhi[4];
                ldsm_x4t(bhi, sbB + off);
#pragma unroll
                for (int mi = 0; mi < 2; mi++) {
                    float* d0 = d[mi][ng * 2];
                    float* d1 = d[mi][ng * 2 + 1];
                    mma16816(d0[0], d0[1], d0[2], d0[3],
                             ahi[mi][0], ahi[mi][1], ahi[mi][2], ahi[mi][3],
                             bhi[0], bhi[1]);
                    mma16816(d0[0], d0[1], d0[2], d0[3],
                             alo[mi][0], alo[mi][1], alo[mi][2], alo[mi][3],
                             bhi[0], bhi[1]);
                    mma16816(d1[0], d1[1], d1[2], d1[3],
                             ahi[mi][0], ahi[mi][1], ahi[mi][2], ahi[mi][3],
                             bhi[2], bhi[3]);
                    mma16816(d1[0], d1[1], d1[2], d1[3],
                             alo[mi][0], alo[mi][1], alo[mi][2], alo[mi][3],
                             bhi[2], bhi[3]);
                }
            }
        }
        __syncthreads();   // fc1 done: A[(ch)&1] reusable, B[ch&1] reusable

        if (ch + 2 < NCHUNKS) {
            const int kc = (ch + 2) * 32;
            const uint32_t sb = pool_u + OFF_B + (ch & 1) * 8192;
            CP_ASYNC16(sb + oB0, gBhi + (size_t)kc * 128);
            CP_ASYNC16(sb + oB1, gBhi + (size_t)kc * 128 + 8);
        }
        CP_COMMIT();
    }

    CP_WAIT0();
    __syncthreads();

    // ---------------- epilogue ----------------
    float* h1 = (float*)poolA;              // [128][129]
    float* h2 = (float*)(poolA + 66560);    // [128][65]

    {
#pragma unroll
        for (int mi = 0; mi < 2; mi++) {
#pragma unroll
            for (int nj = 0; nj < 8; nj++) {
                int m = wm * 32 + mi * 16 + dg;
                int n = wn * 64 + nj * 8 + t2;
                h1[m * 129 + n]           = fmaxf(d[mi][nj][0] + biasS[n], 0.f);
                h1[m * 129 + n + 1]       = fmaxf(d[mi][nj][1] + biasS[n + 1], 0.f);
                h1[(m + 8) * 129 + n]     = fmaxf(d[mi][nj][2] + biasS[n], 0.f);
                h1[(m + 8) * 129 + n + 1] = fmaxf(d[mi][nj][3] + biasS[n + 1], 0.f);
            }
        }
    }
    __syncthreads();

    // layer2
#pragma unroll 1
    for (int it = 0; it < 32; it++) {
        int idx = it * 256 + tid;
        int bd = idx >> 6, o = idx & 63;
        int oo = o & 31;
        const float* h1b  = h1 + bd * 129 + ((o < 32) ? 0 : 64);
        const float* wmat = (o < 32) ? pw2 : vw2;
        float s = (o < 32) ? pb2[oo] : vb2[oo];
#pragma unroll 8
        for (int k = 0; k < 64; k++) s += h1b[k] * wmat[k * 32 + oo];
        h2[bd * 65 + o] = fmaxf(s, 0.f);
    }
    __syncthreads();

    // layer3 + softmax / tanh
    if (tid < 128) {
        int gb = m0 + tid;
        const float* hp = h2 + tid * 65;
        float lg[7];
#pragma unroll
        for (int j = 0; j < 7; j++) {
            float s = pb3[j];
#pragma unroll
            for (int k = 0; k < 32; k++) s += hp[k] * pw3[k * 7 + j];
            lg[j] = s;
        }
        float mx = lg[0];
#pragma unroll
        for (int j = 1; j < 7; j++) mx = fmaxf(mx, lg[j]);
        float se = 0.f;
#pragma unroll
        for (int j = 0; j < 7; j++) { lg[j] = expf(lg[j] - mx); se += lg[j]; }
        float inv = 1.f / se;
#pragma unroll
        for (int j = 0; j < 7; j++) out[(size_t)gb * 7 + j] = lg[j] * inv;

        float v = vb3[0];
#pragma unroll
        for (int k = 0; k < 32; k++) v += hp[32 + k] * vw3[k];
        out[(size_t)BATCH * 7 + gb] = tanhf(v);
    }
}

// =========================================================================
extern "C" void kernel_launch(void* const* d_in, const int* in_sizes, int n_in,
                              void* d_out, int out_size)
{
    const float* x        = (const float*)d_in[0];
    const float* conv_w   = (const float*)d_in[1];
    /* conv_b cancels through batch-norm */
    const float* bn_gamma = (const float*)d_in[3];
    const float* bn_beta  = (const float*)d_in[4];
    const float* pw1 = (const float*)d_in[5];
    const float* pb1 = (const float*)d_in[6];
    const float* pw2 = (const float*)d_in[7];
    const float* pb2 = (const float*)d_in[8];
    const float* pw3 = (const float*)d_in[9];
    const float* pb3 = (const float*)d_in[10];
    const float* vw1 = (const float*)d_in[11];
    const float* vb1 = (const float*)d_in[12];
    const float* vw2 = (const float*)d_in[13];
    const float* vb2 = (const float*)d_in[14];
    const float* vw3 = (const float*)d_in[15];
    const float* vb3 = (const float*)d_in[16];
    float* out = (float*)d_out;

    cudaFuncSetAttribute(k_fused, cudaFuncAttributeMaxDynamicSharedMemorySize, SMEM_DYN);

    k_moments<<<NBLK_MOM, 256>>>(x);
    k_finalize<<<1, 256>>>(conv_w, bn_gamma, bn_beta);
    k_prep<<<FLAT, 128>>>(pw1, vw1);
    k_fused<<<BATCH / 128, 256, SMEM_DYN>>>(x, pb1, vb1, pw2, pb2, pw3, pb3,
                                            vw2, vb2, vw3, vb3, out);
}

// round 6
// speedup vs baseline: 2.1452x; 1.2399x over previous
#include <cuda_runtime.h>
#include <cuda_fp16.h>
#include <cstdint>

#define BATCH 32768
#define NCH   256
#define FLAT  3072
#define NRED  152
#define NBLK_MOM 128
#define EPSV  1e-5f

// ---------------- device scratch ----------------
__device__ float g_part[NBLK_MOM][NRED];
__device__ float g_wscaled[NCH * 16];
__device__ float g_shift[NCH];
// fc1 weights fp16 (hi only), layout [k'][n], k' = p*256 + c
__device__ __half g_w1hi[FLAT * 128];

// ======================= PTX helpers ==================
__device__ __forceinline__ uint32_t smem_u32(const void* p) {
    uint32_t a;
    asm("{ .reg .u64 t; cvta.to.shared.u64 t, %1; cvt.u32.u64 %0, t; }"
        : "=r"(a) : "l"(p));
    return a;
}
#define CP_ASYNC16(dst, src) \
    asm volatile("cp.async.cg.shared.global [%0], [%1], 16;" \
        :: "r"(dst), "l"(src) : "memory")
#define CP_COMMIT() asm volatile("cp.async.commit_group;" ::: "memory")
#define CP_WAIT1()  asm volatile("cp.async.wait_group 1;" ::: "memory")
#define CP_WAIT0()  asm volatile("cp.async.wait_group 0;" ::: "memory")

__device__ __forceinline__ void ldsm_x4(uint32_t r[4], uint32_t addr) {
    asm volatile("ldmatrix.sync.aligned.m8n8.x4.shared.b16 {%0,%1,%2,%3}, [%4];"
        : "=r"(r[0]), "=r"(r[1]), "=r"(r[2]), "=r"(r[3]) : "r"(addr));
}
__device__ __forceinline__ void ldsm_x4t(uint32_t r[4], uint32_t addr) {
    asm volatile("ldmatrix.sync.aligned.m8n8.x4.trans.shared.b16 {%0,%1,%2,%3}, [%4];"
        : "=r"(r[0]), "=r"(r[1]), "=r"(r[2]), "=r"(r[3]) : "r"(addr));
}
__device__ __forceinline__ void mma16816(float& d0, float& d1, float& d2, float& d3,
                                         uint32_t a0, uint32_t a1, uint32_t a2, uint32_t a3,
                                         uint32_t b0, uint32_t b1) {
    asm volatile(
        "mma.sync.aligned.m16n8k16.row.col.f32.f16.f16.f32 "
        "{%0,%1,%2,%3}, {%4,%5,%6,%7}, {%8,%9}, {%0,%1,%2,%3};"
        : "+f"(d0), "+f"(d1), "+f"(d2), "+f"(d3)
        : "r"(a0), "r"(a1), "r"(a2), "r"(a3), "r"(b0), "r"(b1));
}
__device__ __forceinline__ uint32_t pack_h2(float a, float b) {
    __half ha = __float2half_rn(a), hb = __float2half_rn(b);
    return ((uint32_t)__half_as_ushort(hb) << 16) | __half_as_ushort(ha);
}

// =========================================================================
// K1: patch moments (proven)
// =========================================================================
__global__ void k_moments(const float* __restrict__ x)
{
    int b = blockIdx.x * 256 + threadIdx.x;
    const float* xb = x + b * 42;
    float xv[42];
#pragma unroll
    for (int i = 0; i < 42; i++) xv[i] = xb[i];

    __shared__ float red[8][NRED];
    int lane = threadIdx.x & 31;
    int warp = threadIdx.x >> 5;

    int idx = 0;
#pragma unroll
    for (int k = 0; k < 16; k++) {
        float s = 0.f;
#pragma unroll
        for (int r = 0; r < 3; r++)
#pragma unroll
            for (int c = 0; c < 4; c++)
                s += xv[(r + (k >> 2)) * 7 + (c + (k & 3))];
#pragma unroll
        for (int o = 16; o; o >>= 1) s += __shfl_xor_sync(0xffffffffu, s, o);
        if (lane == 0) red[warp][idx] = s;
        idx++;
    }
#pragma unroll
    for (int k = 0; k < 16; k++) {
#pragma unroll
        for (int l = k; l < 16; l++) {
            float s = 0.f;
#pragma unroll
            for (int r = 0; r < 3; r++)
#pragma unroll
                for (int c = 0; c < 4; c++)
                    s += xv[(r + (k >> 2)) * 7 + (c + (k & 3))] *
                         xv[(r + (l >> 2)) * 7 + (c + (l & 3))];
#pragma unroll
            for (int o = 16; o; o >>= 1) s += __shfl_xor_sync(0xffffffffu, s, o);
            if (lane == 0) red[warp][idx] = s;
            idx++;
        }
    }
    __syncthreads();
    if (threadIdx.x < NRED) {
        float s = 0.f;
#pragma unroll
        for (int w = 0; w < 8; w++) s += red[w][threadIdx.x];
        g_part[blockIdx.x][threadIdx.x] = s;
    }
}

// =========================================================================
// K2: finalize BN fold (proven)
// =========================================================================
__global__ void k_finalize(const float* __restrict__ conv_w,
                           const float* __restrict__ bn_gamma,
                           const float* __restrict__ bn_beta)
{
    __shared__ float S[NRED];
    int t = threadIdx.x;
    if (t < NRED) {
        float s = 0.f;
        for (int bl = 0; bl < NBLK_MOM; bl++) s += g_part[bl][t];
        S[t] = s * (1.f / (12.f * (float)BATCH));
    }
    __syncthreads();
    if (t < NCH) {
        float w[16];
#pragma unroll
        for (int i = 0; i < 16; i++) w[i] = conv_w[t * 16 + i];
        float mraw = 0.f;
#pragma unroll
        for (int i = 0; i < 16; i++) mraw += w[i] * S[i];
        float q = 0.f;
        int idx = 16;
#pragma unroll
        for (int k = 0; k < 16; k++)
#pragma unroll
            for (int l = k; l < 16; l++) {
                float coef = (k == l) ? (w[k] * w[l]) : (2.f * w[k] * w[l]);
                q += coef * S[idx];
                idx++;
            }
        float var = q - mraw * mraw;
        float a = bn_gamma[t] * rsqrtf(var + EPSV);
#pragma unroll
        for (int i = 0; i < 16; i++) g_wscaled[t * 16 + i] = a * w[i];
        g_shift[t] = bn_beta[t] - a * mraw;
    }
}

// =========================================================================
// K_prep: W1 -> [k'][n] fp16 (hi only).  kp = p*256+c, f = c*12+p.
// =========================================================================
__global__ void k_prep(const float* __restrict__ pw1, const float* __restrict__ vw1)
{
    int kp = blockIdx.x;
    int n  = threadIdx.x;
    int p = kp >> 8, c = kp & 255;
    int f = c * 12 + p;
    float v = (n < 64) ? pw1[(size_t)f * 64 + n] : vw1[(size_t)f * 64 + (n - 64)];
    g_w1hi[(size_t)kp * 128 + n] = __float2half_rn(v);
}

// =========================================================================
// K4: fully-tensor fused kernel, K=64 per iteration (48 iters).
// Per iter (patch p=it>>2, channel groups 2x32):
//   conv: A[128x64] = relu(Xp[128x16] @ Wc + shift), 24 HMMA/warp, hi-only out
//   fc1 : D += Ahi @ Bhi[64x128],                    64 HMMA/warp
// Smem (dyn):
//   0      B bufs   2 x 16384 (64k x 128n fp16, 8-way swizzle)
//   32768  A bufs   2 x 16384 (128m x 64k fp16, 8-way swizzle)
//   65536  Xp hi 6144 (row stride 48) | lo 6144
//   77824  Wc hi 8192 ([16][256] swizzled) | lo 8192
//   94208  shift 1024       total 95232; SMEM_DYN=99840 for epilogue reuse
// Epilogue: h1 [128][129] f32 @0, h2 [128][65] f32 @66560.
// =========================================================================
#define NITER    48
#define OFF_B    0
#define OFF_A    32768
#define OFF_XP   65536
#define OFF_XPL  71680
#define OFF_WC   77824
#define OFF_WCL  86016
#define OFF_SH   94208
#define SMEM_DYN 99840

__global__ __launch_bounds__(256, 2) void k_fused(
    const float* __restrict__ x,
    const float* __restrict__ pb1, const float* __restrict__ vb1,
    const float* __restrict__ pw2, const float* __restrict__ pb2,
    const float* __restrict__ pw3, const float* __restrict__ pb3,
    const float* __restrict__ vw2, const float* __restrict__ vb2,
    const float* __restrict__ vw3, const float* __restrict__ vb3,
    float* __restrict__ out)
{
    extern __shared__ char dyn_pool[];
    __shared__ float biasS[128];

    char* poolA = dyn_pool;
    const uint32_t pool_u = smem_u32(poolA);

    const int tid  = threadIdx.x;
    const int wid  = tid >> 5;
    const int lane = tid & 31;
    const int m0   = blockIdx.x * 128;
    const int wm   = wid & 3;
    const int wn   = wid >> 2;

    float* shiftS = (float*)(poolA + OFF_SH);

    // ---- one-time smem fills ----
    if (tid < 64)       biasS[tid] = pb1[tid];
    else if (tid < 128) biasS[tid] = vb1[tid - 64];
    {   // folded conv weights -> Wc[k][c] fp16 split, swizzled rows of 512B
#pragma unroll
        for (int i = 0; i < 16; i++) {
            int idx = tid + i * 256;
            int k = idx >> 8, c = idx & 255;
            float v = g_wscaled[c * 16 + k];
            __half h = __float2half_rn(v);
            float l = v - __half2float(h);
            uint32_t o = (uint32_t)k * 512 + ((((uint32_t)(c >> 3)) ^ (k & 7)) << 4) + (c & 7) * 2;
            *(__half*)(poolA + OFF_WC + o)  = h;
            *(__half*)(poolA + OFF_WCL + o) = __float2half_rn(l);
        }
    }
    shiftS[tid] = g_shift[tid];

    // ---- fc1 B cp.async lanes: 64 rows x 256B, 4x16B per thread ----
    const int brow = tid >> 2;              // 0..63
    const int bq   = (tid & 3) * 4;         // 16B-chunk base (0,4,8,12)
    const __half* gB = g_w1hi + (size_t)brow * 128 + bq * 8;
    uint32_t oBs[4];
#pragma unroll
    for (int j = 0; j < 4; j++)
        oBs[j] = (uint32_t)brow * 256 + ((((uint32_t)(bq + j)) ^ (brow & 7)) << 4);

    // ---- prologue B(0), B(1) ----
#pragma unroll
    for (int pc = 0; pc < 2; pc++) {
        const uint32_t sb = pool_u + OFF_B + pc * 16384;
        const size_t kofs = (size_t)pc * 64 * 128;
#pragma unroll
        for (int j = 0; j < 4; j++)
            CP_ASYNC16(sb + oBs[j], gB + kofs + j * 8);
        CP_COMMIT();
    }

    // ---- lane constants ----
    const int a_r  = (lane & 15);
    const int a_hg = (lane >> 4);
    const int b_kl = ((lane >> 3) & 1) * 8 + (lane & 7);
    const int b_ng = (lane >> 4);
    const int dg   = lane >> 2;
    const int t2   = (lane & 3) * 2;

    float d[2][8][4];
#pragma unroll
    for (int mi = 0; mi < 2; mi++)
#pragma unroll
        for (int nj = 0; nj < 8; nj++)
#pragma unroll
            for (int q = 0; q < 4; q++) d[mi][nj][q] = 0.f;

    __syncthreads();   // Wc / shift visible

    // ================= Xp build (reads x from global/L1) =================
    auto build_xp = [&](int p) {
        int row = tid >> 1;
        int chk = tid & 1;
        const float* xw = x + (size_t)(m0 + row) * 42 + (p >> 2) * 7 + (p & 3);
        uint32_t hp[4], lp[4];
#pragma unroll
        for (int j = 0; j < 4; j++) {
            int k0 = chk * 8 + j * 2, k1 = k0 + 1;
            float v0 = xw[(k0 >> 2) * 7 + (k0 & 3)];
            float v1 = xw[(k1 >> 2) * 7 + (k1 & 3)];
            __half h0 = __float2half_rn(v0), h1 = __float2half_rn(v1);
            hp[j] = ((uint32_t)__half_as_ushort(h1) << 16) | __half_as_ushort(h0);
            lp[j] = pack_h2(v0 - __half2float(h0), v1 - __half2float(h1));
        }
        uint32_t o = (uint32_t)row * 48 + chk * 16;
        *(uint4*)(poolA + OFF_XP + o)  = make_uint4(hp[0], hp[1], hp[2], hp[3]);
        *(uint4*)(poolA + OFF_XPL + o) = make_uint4(lp[0], lp[1], lp[2], lp[3]);
    };

    // ================= conv for one 64-K iteration =======================
    auto conv_chunk = [&](int it) {
        char* abuf = poolA + OFF_A + (it & 1) * 16384;
        uint32_t xaddr = pool_u + OFF_XP + (uint32_t)(wid * 16 + a_r) * 48 + a_hg * 16;
        uint32_t xhi[4], xlo[4];
        ldsm_x4(xhi, xaddr);
        ldsm_x4(xlo, xaddr + 6144);

        const int r0 = wid * 16 + dg;
        const int r1 = r0 + 8;
        const uint32_t key0 = (uint32_t)(r0 & 7);
        const uint32_t key1 = (uint32_t)(r1 & 7);

#pragma unroll
        for (int g = 0; g < 2; g++) {
            const int grp = (it & 3) * 2 + g;   // 0..7 channel group of 32
            const int c0  = grp * 32;
            const int bg  = grp * 4;

            float cd[4][4];
#pragma unroll
            for (int nt = 0; nt < 4; nt++)
#pragma unroll
                for (int q = 0; q < 4; q++) cd[nt][q] = 0.f;

#pragma unroll
            for (int nt2 = 0; nt2 < 2; nt2++) {
                uint32_t woff = (uint32_t)b_kl * 512 +
                                ((((uint32_t)(bg + nt2 * 2 + b_ng)) ^ (b_kl & 7)) << 4);
                uint32_t whi[4], wlo[4];
                ldsm_x4t(whi, pool_u + OFF_WC + woff);
                ldsm_x4t(wlo, pool_u + OFF_WCL + woff);
#pragma unroll
                for (int sub = 0; sub < 2; sub++) {
                    float* cdn = cd[nt2 * 2 + sub];
                    mma16816(cdn[0], cdn[1], cdn[2], cdn[3],
                             xhi[0], xhi[1], xhi[2], xhi[3], whi[2 * sub], whi[2 * sub + 1]);
                    mma16816(cdn[0], cdn[1], cdn[2], cdn[3],
                             xlo[0], xlo[1], xlo[2], xlo[3], whi[2 * sub], whi[2 * sub + 1]);
                    mma16816(cdn[0], cdn[1], cdn[2], cdn[3],
                             xhi[0], xhi[1], xhi[2], xhi[3], wlo[2 * sub], wlo[2 * sub + 1]);
                }
            }

            // repack: shift + ReLU + fp16 round (hi only), 8-way swizzled
#pragma unroll
            for (int nt = 0; nt < 4; nt++) {
                float2 sv = *(const float2*)&shiftS[c0 + nt * 8 + t2];
                float v00 = fmaxf(cd[nt][0] + sv.x, 0.f);
                float v01 = fmaxf(cd[nt][1] + sv.y, 0.f);
                float v10 = fmaxf(cd[nt][2] + sv.x, 0.f);
                float v11 = fmaxf(cd[nt][3] + sv.y, 0.f);
                uint32_t hi0 = pack_h2(v00, v01);
                uint32_t hi1 = pack_h2(v10, v11);
                uint32_t ck  = (uint32_t)(g * 4 + nt);
                uint32_t o0 = (uint32_t)r0 * 128 + ((ck ^ key0) << 4) + (lane & 3) * 4;
                uint32_t o1 = (uint32_t)r1 * 128 + ((ck ^ key1) << 4) + (lane & 3) * 4;
                *(uint32_t*)(abuf + o0) = hi0;
                *(uint32_t*)(abuf + o1) = hi1;
            }
        }
    };

    // ---- prologue: Xp(0), conv iter 0 ----
    build_xp(0);
    __syncthreads();
    conv_chunk(0);

    // ================= main loop =================
#pragma unroll 1
    for (int it = 0; it < NITER; it++) {
        if (it + 1 < NITER) {
            if (((it + 1) & 3) == 0) {
                build_xp((it + 1) >> 2);
                __syncthreads();
            }
            conv_chunk(it + 1);
        }

        CP_WAIT1();
        __syncthreads();   // B[it] ready; A[it] visible

        const uint32_t sbB = pool_u + OFF_B + (it & 1) * 16384;
        const uint32_t sbA = pool_u + OFF_A + (it & 1) * 16384;

#pragma unroll
        for (int ks = 0; ks < 4; ks++) {
            uint32_t a[2][4];
#pragma unroll
            for (int mi = 0; mi < 2; mi++) {
                int row = wm * 32 + mi * 16 + a_r;
                uint32_t chunk = (uint32_t)(ks * 2 + a_hg);
                uint32_t off = (uint32_t)row * 128 + ((chunk ^ (row & 7)) << 4);
                ldsm_x4(a[mi], sbA + off);
            }
#pragma unroll
            for (int ng = 0; ng < 4; ng++) {
                int k = ks * 16 + b_kl;
                uint32_t ncg = (uint32_t)(wn * 8 + ng * 2 + b_ng);
                uint32_t off = (uint32_t)k * 256 + ((ncg ^ (k & 7)) << 4);
                uint32_t bhi[4];
                ldsm_x4t(bhi, sbB + off);
#pragma unroll
                for (int mi = 0; mi < 2; mi++) {
                    float* d0 = d[mi][ng * 2];
                    float* d1 = d[mi][ng * 2 + 1];
                    mma16816(d0[0], d0[1], d0[2], d0[3],
                             a[mi][0], a[mi][1], a[mi][2], a[mi][3], bhi[0], bhi[1]);
                    mma16816(d1[0], d1[1], d1[2], d1[3],
                             a[mi][0], a[mi][1], a[mi][2], a[mi][3], bhi[2], bhi[3]);
                }
            }
        }
        __syncthreads();   // fc1 done: A[it&1], B[it&1] reusable

        if (it + 2 < NITER) {
            const uint32_t sb = pool_u + OFF_B + (it & 1) * 16384;
            const size_t kofs = (size_t)(it + 2) * 64 * 128;
#pragma unroll
            for (int j = 0; j < 4; j++)
                CP_ASYNC16(sb + oBs[j], gB + kofs + j * 8);
        }
        CP_COMMIT();
    }

    CP_WAIT0();
    __syncthreads();

    // ---------------- epilogue ----------------
    float* h1 = (float*)poolA;              // [128][129]
    float* h2 = (float*)(poolA + 66560);    // [128][65]

    {
#pragma unroll
        for (int mi = 0; mi < 2; mi++) {
#pragma unroll
            for (int nj = 0; nj < 8; nj++) {
                int m = wm * 32 + mi * 16 + dg;
                int n = wn * 64 + nj * 8 + t2;
                h1[m * 129 + n]           = fmaxf(d[mi][nj][0] + biasS[n], 0.f);
                h1[m * 129 + n + 1]       = fmaxf(d[mi][nj][1] + biasS[n + 1], 0.f);
                h1[(m + 8) * 129 + n]     = fmaxf(d[mi][nj][2] + biasS[n], 0.f);
                h1[(m + 8) * 129 + n + 1] = fmaxf(d[mi][nj][3] + biasS[n + 1], 0.f);
            }
        }
    }
    __syncthreads();

    // layer2
#pragma unroll 1
    for (int it = 0; it < 32; it++) {
        int idx = it * 256 + tid;
        int bd = idx >> 6, o = idx & 63;
        int oo = o & 31;
        const float* h1b  = h1 + bd * 129 + ((o < 32) ? 0 : 64);
        const float* wmat = (o < 32) ? pw2 : vw2;
        float s = (o < 32) ? pb2[oo] : vb2[oo];
#pragma unroll 8
        for (int k = 0; k < 64; k++) s += h1b[k] * wmat[k * 32 + oo];
        h2[bd * 65 + o] = fmaxf(s, 0.f);
    }
    __syncthreads();

    // layer3 + softmax / tanh
    if (tid < 128) {
        int gb = m0 + tid;
        const float* hp = h2 + tid * 65;
        float lg[7];
#pragma unroll
        for (int j = 0; j < 7; j++) {
            float s = pb3[j];
#pragma unroll
            for (int k = 0; k < 32; k++) s += hp[k] * pw3[k * 7 + j];
            lg[j] = s;
        }
        float mx = lg[0];
#pragma unroll
        for (int j = 1; j < 7; j++) mx = fmaxf(mx, lg[j]);
        float se = 0.f;
#pragma unroll
        for (int j = 0; j < 7; j++) { lg[j] = expf(lg[j] - mx); se += lg[j]; }
        float inv = 1.f / se;
#pragma unroll
        for (int j = 0; j < 7; j++) out[(size_t)gb * 7 + j] = lg[j] * inv;

        float v = vb3[0];
#pragma unroll
        for (int k = 0; k < 32; k++) v += hp[32 + k] * vw3[k];
        out[(size_t)BATCH * 7 + gb] = tanhf(v);
    }
}

// =========================================================================
extern "C" void kernel_launch(void* const* d_in, const int* in_sizes, int n_in,
                              void* d_out, int out_size)
{
    const float* x        = (const float*)d_in[0];
    const float* conv_w   = (const float*)d_in[1];
    /* conv_b cancels through batch-norm */
    const float* bn_gamma = (const float*)d_in[3];
    const float* bn_beta  = (const float*)d_in[4];
    const float* pw1 = (const float*)d_in[5];
    const float* pb1 = (const float*)d_in[6];
    const float* pw2 = (const float*)d_in[7];
    const float* pb2 = (const float*)d_in[8];
    const float* pw3 = (const float*)d_in[9];
    const float* pb3 = (const float*)d_in[10];
    const float* vw1 = (const float*)d_in[11];
    const float* vb1 = (const float*)d_in[12];
    const float* vw2 = (const float*)d_in[13];
    const float* vb2 = (const float*)d_in[14];
    const float* vw3 = (const float*)d_in[15];
    const float* vb3 = (const float*)d_in[16];
    float* out = (float*)d_out;

    cudaFuncSetAttribute(k_fused, cudaFuncAttributeMaxDynamicSharedMemorySize, SMEM_DYN);

    k_moments<<<NBLK_MOM, 256>>>(x);
    k_finalize<<<1, 256>>>(conv_w, bn_gamma, bn_beta);
    k_prep<<<FLAT, 128>>>(pw1, vw1);
    k_fused<<<BATCH / 128, 256, SMEM_DYN>>>(x, pb1, vb1, pw2, pb2, pw3, pb3,
                                            vw2, vb2, vw3, vb3, out);
}

// round 7
// speedup vs baseline: 2.2084x; 1.0295x over previous
#include <cuda_runtime.h>
#include <cuda_fp16.h>
#include <cstdint>

#define BATCH 32768
#define NCH   256
#define FLAT  3072
#define NRED  152
#define NBLK_MOM 128
#define EPSV  1e-5f

// ---------------- device scratch ----------------
__device__ float g_part[NBLK_MOM][NRED];
__device__ float g_wscaled[NCH * 16];
__device__ float g_shift[NCH];
// fc1 weights fp16 (hi only), layout [k'][n], k' = p*256 + c  (linear: k' = it*64 + local)
__device__ __half g_w1hi[FLAT * 128];

// ======================= PTX helpers ==================
__device__ __forceinline__ uint32_t smem_u32(const void* p) {
    uint32_t a;
    asm("{ .reg .u64 t; cvta.to.shared.u64 t, %1; cvt.u32.u64 %0, t; }"
        : "=r"(a) : "l"(p));
    return a;
}
#define CP_ASYNC16(dst, src) \
    asm volatile("cp.async.cg.shared.global [%0], [%1], 16;" \
        :: "r"(dst), "l"(src) : "memory")
#define CP_COMMIT() asm volatile("cp.async.commit_group;" ::: "memory")
#define CP_WAIT1()  asm volatile("cp.async.wait_group 1;" ::: "memory")
#define CP_WAIT0()  asm volatile("cp.async.wait_group 0;" ::: "memory")

__device__ __forceinline__ void ldsm_x4t(uint32_t r[4], uint32_t addr) {
    asm volatile("ldmatrix.sync.aligned.m8n8.x4.trans.shared.b16 {%0,%1,%2,%3}, [%4];"
        : "=r"(r[0]), "=r"(r[1]), "=r"(r[2]), "=r"(r[3]) : "r"(addr));
}
__device__ __forceinline__ void mma16816(float& d0, float& d1, float& d2, float& d3,
                                         uint32_t a0, uint32_t a1, uint32_t a2, uint32_t a3,
                                         uint32_t b0, uint32_t b1) {
    asm volatile(
        "mma.sync.aligned.m16n8k16.row.col.f32.f16.f16.f32 "
        "{%0,%1,%2,%3}, {%4,%5,%6,%7}, {%8,%9}, {%0,%1,%2,%3};"
        : "+f"(d0), "+f"(d1), "+f"(d2), "+f"(d3)
        : "r"(a0), "r"(a1), "r"(a2), "r"(a3), "r"(b0), "r"(b1));
}
__device__ __forceinline__ uint32_t pack_h2(float a, float b) {
    __half ha = __float2half_rn(a), hb = __float2half_rn(b);
    return ((uint32_t)__half_as_ushort(hb) << 16) | __half_as_ushort(ha);
}

// =========================================================================
// K1: patch moments (proven)
// =========================================================================
__global__ void k_moments(const float* __restrict__ x)
{
    int b = blockIdx.x * 256 + threadIdx.x;
    const float* xb = x + b * 42;
    float xv[42];
#pragma unroll
    for (int i = 0; i < 42; i++) xv[i] = xb[i];

    __shared__ float red[8][NRED];
    int lane = threadIdx.x & 31;
    int warp = threadIdx.x >> 5;

    int idx = 0;
#pragma unroll
    for (int k = 0; k < 16; k++) {
        float s = 0.f;
#pragma unroll
        for (int r = 0; r < 3; r++)
#pragma unroll
            for (int c = 0; c < 4; c++)
                s += xv[(r + (k >> 2)) * 7 + (c + (k & 3))];
#pragma unroll
        for (int o = 16; o; o >>= 1) s += __shfl_xor_sync(0xffffffffu, s, o);
        if (lane == 0) red[warp][idx] = s;
        idx++;
    }
#pragma unroll
    for (int k = 0; k < 16; k++) {
#pragma unroll
        for (int l = k; l < 16; l++) {
            float s = 0.f;
#pragma unroll
            for (int r = 0; r < 3; r++)
#pragma unroll
                for (int c = 0; c < 4; c++)
                    s += xv[(r + (k >> 2)) * 7 + (c + (k & 3))] *
                         xv[(r + (l >> 2)) * 7 + (c + (l & 3))];
#pragma unroll
            for (int o = 16; o; o >>= 1) s += __shfl_xor_sync(0xffffffffu, s, o);
            if (lane == 0) red[warp][idx] = s;
            idx++;
        }
    }
    __syncthreads();
    if (threadIdx.x < NRED) {
        float s = 0.f;
#pragma unroll
        for (int w = 0; w < 8; w++) s += red[w][threadIdx.x];
        g_part[blockIdx.x][threadIdx.x] = s;
    }
}

// =========================================================================
// K2: finalize BN fold (proven)
// =========================================================================
__global__ void k_finalize(const float* __restrict__ conv_w,
                           const float* __restrict__ bn_gamma,
                           const float* __restrict__ bn_beta)
{
    __shared__ float S[NRED];
    int t = threadIdx.x;
    if (t < NRED) {
        float s = 0.f;
        for (int bl = 0; bl < NBLK_MOM; bl++) s += g_part[bl][t];
        S[t] = s * (1.f / (12.f * (float)BATCH));
    }
    __syncthreads();
    if (t < NCH) {
        float w[16];
#pragma unroll
        for (int i = 0; i < 16; i++) w[i] = conv_w[t * 16 + i];
        float mraw = 0.f;
#pragma unroll
        for (int i = 0; i < 16; i++) mraw += w[i] * S[i];
        float q = 0.f;
        int idx = 16;
#pragma unroll
        for (int k = 0; k < 16; k++)
#pragma unroll
            for (int l = k; l < 16; l++) {
                float coef = (k == l) ? (w[k] * w[l]) : (2.f * w[k] * w[l]);
                q += coef * S[idx];
                idx++;
            }
        float var = q - mraw * mraw;
        float a = bn_gamma[t] * rsqrtf(var + EPSV);
#pragma unroll
        for (int i = 0; i < 16; i++) g_wscaled[t * 16 + i] = a * w[i];
        g_shift[t] = bn_beta[t] - a * mraw;
    }
}

// =========================================================================
// K_prep: W1 -> [k'][n] fp16 (hi only).  kp = p*256+c, f = c*12+p.
// =========================================================================
__global__ void k_prep(const float* __restrict__ pw1, const float* __restrict__ vw1)
{
    int kp = blockIdx.x;
    int n  = threadIdx.x;
    int p = kp >> 8, c = kp & 255;
    int f = c * 12 + p;
    float v = (n < 64) ? pw1[(size_t)f * 64 + n] : vw1[(size_t)f * 64 + (n - 64)];
    g_w1hi[(size_t)kp * 128 + n] = __float2half_rn(v);
}

// =========================================================================
// K4: register-dataflow fused kernel. Each warp owns m16 x n128.
// Per iter (K=64): conv 24 HMMA -> A-frags in registers -> fc1 64 HMMA.
// Smem (dyn): B ring 3 x 16384 @0 | Wc hi @49152, lo @57344 | shift @65536
//             epilogue reuse: h1 [128][129] f32 @0, h2 [128][65] @66560
// =========================================================================
#define NITER    48
#define OFF_B    0
#define OFF_WC   49152
#define OFF_WCL  57344
#define OFF_SH   65536
#define SMEM_DYN 99840

__global__ __launch_bounds__(256, 2) void k_fused(
    const float* __restrict__ x,
    const float* __restrict__ pb1, const float* __restrict__ vb1,
    const float* __restrict__ pw2, const float* __restrict__ pb2,
    const float* __restrict__ pw3, const float* __restrict__ pb3,
    const float* __restrict__ vw2, const float* __restrict__ vb2,
    const float* __restrict__ vw3, const float* __restrict__ vb3,
    float* __restrict__ out)
{
    extern __shared__ char dyn_pool[];
    __shared__ float biasS[128];

    char* poolA = dyn_pool;
    const uint32_t pool_u = smem_u32(poolA);

    const int tid  = threadIdx.x;
    const int wid  = tid >> 5;
    const int lane = tid & 31;
    const int m0   = blockIdx.x * 128;

    float* shiftS = (float*)(poolA + OFF_SH);

    // ---- one-time smem fills ----
    if (tid < 64)       biasS[tid] = pb1[tid];
    else if (tid < 128) biasS[tid] = vb1[tid - 64];
    {   // folded conv weights -> Wc[k][c] fp16 split, swizzled rows of 512B
#pragma unroll
        for (int i = 0; i < 16; i++) {
            int idx = tid + i * 256;
            int k = idx >> 8, c = idx & 255;
            float v = g_wscaled[c * 16 + k];
            __half h = __float2half_rn(v);
            float l = v - __half2float(h);
            uint32_t o = (uint32_t)k * 512 + ((((uint32_t)(c >> 3)) ^ (k & 7)) << 4) + (c & 7) * 2;
            *(__half*)(poolA + OFF_WC + o)  = h;
            *(__half*)(poolA + OFF_WCL + o) = __float2half_rn(l);
        }
    }
    shiftS[tid] = g_shift[tid];

    // ---- fc1 B cp.async lanes: 64 rows x 256B, 4x16B per thread ----
    const int brow = tid >> 2;
    const int bq   = (tid & 3) * 4;
    const __half* gB = g_w1hi + (size_t)brow * 128 + bq * 8;
    uint32_t oBs[4];
#pragma unroll
    for (int j = 0; j < 4; j++)
        oBs[j] = (uint32_t)brow * 256 + ((((uint32_t)(bq + j)) ^ (brow & 7)) << 4);

    // ---- prologue B(0), B(1) into ring slots 0,1 ----
#pragma unroll
    for (int pc = 0; pc < 2; pc++) {
        const uint32_t sb = pool_u + OFF_B + pc * 16384;
        const size_t kofs = (size_t)pc * 64 * 128;
#pragma unroll
        for (int j = 0; j < 4; j++)
            CP_ASYNC16(sb + oBs[j], gB + kofs + j * 8);
        CP_COMMIT();
    }

    // ---- lane constants ----
    const int g    = lane >> 2;            // frag row
    const int t2   = (lane & 3) * 2;       // frag col pair
    const int b_kl = ((lane >> 3) & 1) * 8 + (lane & 7);
    const int b_ng = (lane >> 4);

    // D accumulators: m16 x n128 per warp = 16 n8-tiles
    float d[16][4];
#pragma unroll
    for (int nt = 0; nt < 16; nt++)
#pragma unroll
        for (int q = 0; q < 4; q++) d[nt][q] = 0.f;

    __syncthreads();   // Wc / shift visible

    // x-fragment registers (conv A operand, rebuilt per patch)
    uint32_t xhi[4], xlo[4];
    {
        // initial build for patch 0 (offsets recomputed inside loop too)
        const float* xb = x + (size_t)(m0 + wid * 16) * 42;
        int o0 = ((t2 >> 2) * 7 + (t2 & 3));
        int k1 = t2 + 8;
        int o1 = ((k1 >> 2) * 7 + (k1 & 3));
        float a0x = xb[(size_t)g * 42 + o0],     a0y = xb[(size_t)g * 42 + o0 + 1];
        float a1x = xb[(size_t)(g + 8) * 42 + o0], a1y = xb[(size_t)(g + 8) * 42 + o0 + 1];
        float a2x = xb[(size_t)g * 42 + o1],     a2y = xb[(size_t)g * 42 + o1 + 1];
        float a3x = xb[(size_t)(g + 8) * 42 + o1], a3y = xb[(size_t)(g + 8) * 42 + o1 + 1];
        xhi[0] = pack_h2(a0x, a0y); xhi[1] = pack_h2(a1x, a1y);
        xhi[2] = pack_h2(a2x, a2y); xhi[3] = pack_h2(a3x, a3y);
        xlo[0] = pack_h2(a0x - __half2float(__float2half_rn(a0x)), a0y - __half2float(__float2half_rn(a0y)));
        xlo[1] = pack_h2(a1x - __half2float(__float2half_rn(a1x)), a1y - __half2float(__float2half_rn(a1y)));
        xlo[2] = pack_h2(a2x - __half2float(__float2half_rn(a2x)), a2y - __half2float(__float2half_rn(a2y)));
        xlo[3] = pack_h2(a3x - __half2float(__float2half_rn(a3x)), a3y - __half2float(__float2half_rn(a3y)));
    }

    // ================= main loop =================
#pragma unroll 1
    for (int it = 0; it < NITER; it++) {
        CP_WAIT1();
        __syncthreads();   // B[it%3] arrived & visible; all warps past fc1(it-1)

        // issue B(it+2) into ring slot (it+2)%3
        if (it + 2 < NITER) {
            const uint32_t sb = pool_u + OFF_B + ((it + 2) % 3) * 16384;
            const size_t kofs = (size_t)(it + 2) * 64 * 128;
#pragma unroll
            for (int j = 0; j < 4; j++)
                CP_ASYNC16(sb + oBs[j], gB + kofs + j * 8);
        }
        CP_COMMIT();

        // rebuild x-fragments at patch boundary (registers only, no sync)
        if (it > 0 && (it & 3) == 0) {
            const int p = it >> 2;
            const float* xb = x + (size_t)(m0 + wid * 16) * 42 + (p >> 2) * 7 + (p & 3);
            int o0 = ((t2 >> 2) * 7 + (t2 & 3));
            int k1 = t2 + 8;
            int o1 = ((k1 >> 2) * 7 + (k1 & 3));
            float a0x = xb[(size_t)g * 42 + o0],     a0y = xb[(size_t)g * 42 + o0 + 1];
            float a1x = xb[(size_t)(g + 8) * 42 + o0], a1y = xb[(size_t)(g + 8) * 42 + o0 + 1];
            float a2x = xb[(size_t)g * 42 + o1],     a2y = xb[(size_t)g * 42 + o1 + 1];
            float a3x = xb[(size_t)(g + 8) * 42 + o1], a3y = xb[(size_t)(g + 8) * 42 + o1 + 1];
            xhi[0] = pack_h2(a0x, a0y); xhi[1] = pack_h2(a1x, a1y);
            xhi[2] = pack_h2(a2x, a2y); xhi[3] = pack_h2(a3x, a3y);
            xlo[0] = pack_h2(a0x - __half2float(__float2half_rn(a0x)), a0y - __half2float(__float2half_rn(a0y)));
            xlo[1] = pack_h2(a1x - __half2float(__float2half_rn(a1x)), a1y - __half2float(__float2half_rn(a1y)));
            xlo[2] = pack_h2(a2x - __half2float(__float2half_rn(a2x)), a2y - __half2float(__float2half_rn(a2y)));
            xlo[3] = pack_h2(a3x - __half2float(__float2half_rn(a3x)), a3y - __half2float(__float2half_rn(a3y)));
        }

        // ---- conv: 2 channel groups -> 4 fc1 A-fragments (registers) ----
        uint32_t afr[4][4];
#pragma unroll
        for (int gg = 0; gg < 2; gg++) {
            const int grp = (it & 3) * 2 + gg;
            const int bg  = grp * 4;
            float cd[4][4];
#pragma unroll
            for (int nt = 0; nt < 4; nt++)
#pragma unroll
                for (int q = 0; q < 4; q++) cd[nt][q] = 0.f;
#pragma unroll
            for (int nt2 = 0; nt2 < 2; nt2++) {
                uint32_t woff = (uint32_t)b_kl * 512 +
                                ((((uint32_t)(bg + nt2 * 2 + b_ng)) ^ (b_kl & 7)) << 4);
                uint32_t whi[4], wlo[4];
                ldsm_x4t(whi, pool_u + OFF_WC + woff);
                ldsm_x4t(wlo, pool_u + OFF_WCL + woff);
#pragma unroll
                for (int sub = 0; sub < 2; sub++) {
                    float* cdn = cd[nt2 * 2 + sub];
                    mma16816(cdn[0], cdn[1], cdn[2], cdn[3],
                             xhi[0], xhi[1], xhi[2], xhi[3], whi[2 * sub], whi[2 * sub + 1]);
                    mma16816(cdn[0], cdn[1], cdn[2], cdn[3],
                             xlo[0], xlo[1], xlo[2], xlo[3], whi[2 * sub], whi[2 * sub + 1]);
                    mma16816(cdn[0], cdn[1], cdn[2], cdn[3],
                             xhi[0], xhi[1], xhi[2], xhi[3], wlo[2 * sub], wlo[2 * sub + 1]);
                }
            }
            // repack: shift + ReLU + fp16 -> A-frags for k16 chunks 2gg, 2gg+1
#pragma unroll
            for (int pr = 0; pr < 2; pr++) {
                const float* t0 = cd[pr * 2];
                const float* t1 = cd[pr * 2 + 1];
                float2 s0 = *(const float2*)&shiftS[grp * 32 + pr * 16 + t2];
                float2 s1 = *(const float2*)&shiftS[grp * 32 + pr * 16 + 8 + t2];
                uint32_t* af = afr[gg * 2 + pr];
                af[0] = pack_h2(fmaxf(t0[0] + s0.x, 0.f), fmaxf(t0[1] + s0.y, 0.f));
                af[1] = pack_h2(fmaxf(t0[2] + s0.x, 0.f), fmaxf(t0[3] + s0.y, 0.f));
                af[2] = pack_h2(fmaxf(t1[0] + s1.x, 0.f), fmaxf(t1[1] + s1.y, 0.f));
                af[3] = pack_h2(fmaxf(t1[2] + s1.x, 0.f), fmaxf(t1[3] + s1.y, 0.f));
            }
        }

        // ---- fc1: D[16 tiles] += A(4 kk-frags) @ B[64x128] ----
        const uint32_t sbB = pool_u + OFF_B + (it % 3) * 16384;
#pragma unroll
        for (int kk = 0; kk < 4; kk++) {
            const int k = kk * 16 + b_kl;
            const uint32_t* af = afr[kk];
#pragma unroll
            for (int np = 0; np < 8; np++) {
                uint32_t ncg = (uint32_t)(np * 2 + b_ng);
                uint32_t off = (uint32_t)k * 256 + ((ncg ^ (k & 7)) << 4);
                uint32_t bhi[4];
                ldsm_x4t(bhi, sbB + off);
                mma16816(d[np * 2][0], d[np * 2][1], d[np * 2][2], d[np * 2][3],
                         af[0], af[1], af[2], af[3], bhi[0], bhi[1]);
                mma16816(d[np * 2 + 1][0], d[np * 2 + 1][1], d[np * 2 + 1][2], d[np * 2 + 1][3],
                         af[0], af[1], af[2], af[3], bhi[2], bhi[3]);
            }
        }
    }

    CP_WAIT0();
    __syncthreads();   // all fc1 done; smem reusable for epilogue

    // ---------------- epilogue ----------------
    float* h1 = (float*)poolA;              // [128][129]
    float* h2 = (float*)(poolA + 66560);    // [128][65]

    {
        const int m = wid * 16 + g;
#pragma unroll
        for (int nt = 0; nt < 16; nt++) {
            int n = nt * 8 + t2;
            h1[m * 129 + n]           = fmaxf(d[nt][0] + biasS[n], 0.f);
            h1[m * 129 + n + 1]       = fmaxf(d[nt][1] + biasS[n + 1], 0.f);
            h1[(m + 8) * 129 + n]     = fmaxf(d[nt][2] + biasS[n], 0.f);
            h1[(m + 8) * 129 + n + 1] = fmaxf(d[nt][3] + biasS[n + 1], 0.f);
        }
    }
    __syncthreads();

    // layer2
#pragma unroll 1
    for (int it = 0; it < 32; it++) {
        int idx = it * 256 + tid;
        int bd = idx >> 6, o = idx & 63;
        int oo = o & 31;
        const float* h1b  = h1 + bd * 129 + ((o < 32) ? 0 : 64);
        const float* wmat = (o < 32) ? pw2 : vw2;
        float s = (o < 32) ? pb2[oo] : vb2[oo];
#pragma unroll 8
        for (int k = 0; k < 64; k++) s += h1b[k] * wmat[k * 32 + oo];
        h2[bd * 65 + o] = fmaxf(s, 0.f);
    }
    __syncthreads();

    // layer3 + softmax / tanh
    if (tid < 128) {
        int gb = m0 + tid;
        const float* hp = h2 + tid * 65;
        float lg[7];
#pragma unroll
        for (int j = 0; j < 7; j++) {
            float s = pb3[j];
#pragma unroll
            for (int k = 0; k < 32; k++) s += hp[k] * pw3[k * 7 + j];
            lg[j] = s;
        }
        float mx = lg[0];
#pragma unroll
        for (int j = 1; j < 7; j++) mx = fmaxf(mx, lg[j]);
        float se = 0.f;
#pragma unroll
        for (int j = 0; j < 7; j++) { lg[j] = expf(lg[j] - mx); se += lg[j]; }
        float inv = 1.f / se;
#pragma unroll
        for (int j = 0; j < 7; j++) out[(size_t)gb * 7 + j] = lg[j] * inv;

        float v = vb3[0];
#pragma unroll
        for (int k = 0; k < 32; k++) v += hp[32 + k] * vw3[k];
        out[(size_t)BATCH * 7 + gb] = tanhf(v);
    }
}

// =========================================================================
extern "C" void kernel_launch(void* const* d_in, const int* in_sizes, int n_in,
                              void* d_out, int out_size)
{
    const float* x        = (const float*)d_in[0];
    const float* conv_w   = (const float*)d_in[1];
    /* conv_b cancels through batch-norm */
    const float* bn_gamma = (const float*)d_in[3];
    const float* bn_beta  = (const float*)d_in[4];
    const float* pw1 = (const float*)d_in[5];
    const float* pb1 = (const float*)d_in[6];
    const float* pw2 = (const float*)d_in[7];
    const float* pb2 = (const float*)d_in[8];
    const float* pw3 = (const float*)d_in[9];
    const float* pb3 = (const float*)d_in[10];
    const float* vw1 = (const float*)d_in[11];
    const float* vb1 = (const float*)d_in[12];
    const float* vw2 = (const float*)d_in[13];
    const float* vb2 = (const float*)d_in[14];
    const float* vw3 = (const float*)d_in[15];
    const float* vb3 = (const float*)d_in[16];
    float* out = (float*)d_out;

    cudaFuncSetAttribute(k_fused, cudaFuncAttributeMaxDynamicSharedMemorySize, SMEM_DYN);

    k_moments<<<NBLK_MOM, 256>>>(x);
    k_finalize<<<1, 256>>>(conv_w, bn_gamma, bn_beta);
    k_prep<<<FLAT, 128>>>(pw1, vw1);
    k_fused<<<BATCH / 128, 256, SMEM_DYN>>>(x, pb1, vb1, pw2, pb2, pw3, pb3,
                                            vw2, vb2, vw3, vb3, out);
}

// round 8
// speedup vs baseline: 2.5205x; 1.1413x over previous
#include <cuda_runtime.h>
#include <cuda_fp16.h>
#include <cstdint>

#define BATCH 32768
#define NCH   256
#define FLAT  3072
#define NRED  152
#define NBLK_MOM 128
#define EPSV  1e-5f

// ---------------- device scratch ----------------
__device__ float g_part[NBLK_MOM][NRED];
__device__ float g_wscaled[NCH * 16];
__device__ float g_shift[NCH];
// fc1 weights fp16 (hi only), layout [k'][n], k' = p*256 + c
__device__ __half g_w1hi[FLAT * 128];

// ======================= PTX helpers ==================
__device__ __forceinline__ uint32_t smem_u32(const void* p) {
    uint32_t a;
    asm("{ .reg .u64 t; cvta.to.shared.u64 t, %1; cvt.u32.u64 %0, t; }"
        : "=r"(a) : "l"(p));
    return a;
}
#define CP_ASYNC16(dst, src) \
    asm volatile("cp.async.cg.shared.global [%0], [%1], 16;" \
        :: "r"(dst), "l"(src) : "memory")
#define CP_COMMIT() asm volatile("cp.async.commit_group;" ::: "memory")
#define CP_WAIT1()  asm volatile("cp.async.wait_group 1;" ::: "memory")
#define CP_WAIT0()  asm volatile("cp.async.wait_group 0;" ::: "memory")

__device__ __forceinline__ void ldsm_x4t(uint32_t r[4], uint32_t addr) {
    asm volatile("ldmatrix.sync.aligned.m8n8.x4.trans.shared.b16 {%0,%1,%2,%3}, [%4];"
        : "=r"(r[0]), "=r"(r[1]), "=r"(r[2]), "=r"(r[3]) : "r"(addr));
}
__device__ __forceinline__ void mma16816(float& d0, float& d1, float& d2, float& d3,
                                         uint32_t a0, uint32_t a1, uint32_t a2, uint32_t a3,
                                         uint32_t b0, uint32_t b1) {
    asm volatile(
        "mma.sync.aligned.m16n8k16.row.col.f32.f16.f16.f32 "
        "{%0,%1,%2,%3}, {%4,%5,%6,%7}, {%8,%9}, {%0,%1,%2,%3};"
        : "+f"(d0), "+f"(d1), "+f"(d2), "+f"(d3)
        : "r"(a0), "r"(a1), "r"(a2), "r"(a3), "r"(b0), "r"(b1));
}
__device__ __forceinline__ uint32_t f2h2(float a, float b) {
    __half2 h = __floats2half2_rn(a, b);
    return *reinterpret_cast<uint32_t*>(&h);
}

// =========================================================================
// K1: patch moments (proven)
// =========================================================================
__global__ void k_moments(const float* __restrict__ x)
{
    int b = blockIdx.x * 256 + threadIdx.x;
    const float* xb = x + b * 42;
    float xv[42];
#pragma unroll
    for (int i = 0; i < 42; i++) xv[i] = xb[i];

    __shared__ float red[8][NRED];
    int lane = threadIdx.x & 31;
    int warp = threadIdx.x >> 5;

    int idx = 0;
#pragma unroll
    for (int k = 0; k < 16; k++) {
        float s = 0.f;
#pragma unroll
        for (int r = 0; r < 3; r++)
#pragma unroll
            for (int c = 0; c < 4; c++)
                s += xv[(r + (k >> 2)) * 7 + (c + (k & 3))];
#pragma unroll
        for (int o = 16; o; o >>= 1) s += __shfl_xor_sync(0xffffffffu, s, o);
        if (lane == 0) red[warp][idx] = s;
        idx++;
    }
#pragma unroll
    for (int k = 0; k < 16; k++) {
#pragma unroll
        for (int l = k; l < 16; l++) {
            float s = 0.f;
#pragma unroll
            for (int r = 0; r < 3; r++)
#pragma unroll
                for (int c = 0; c < 4; c++)
                    s += xv[(r + (k >> 2)) * 7 + (c + (k & 3))] *
                         xv[(r + (l >> 2)) * 7 + (c + (l & 3))];
#pragma unroll
            for (int o = 16; o; o >>= 1) s += __shfl_xor_sync(0xffffffffu, s, o);
            if (lane == 0) red[warp][idx] = s;
            idx++;
        }
    }
    __syncthreads();
    if (threadIdx.x < NRED) {
        float s = 0.f;
#pragma unroll
        for (int w = 0; w < 8; w++) s += red[w][threadIdx.x];
        g_part[blockIdx.x][threadIdx.x] = s;
    }
}

// =========================================================================
// K2: finalize BN fold (proven)
// =========================================================================
__global__ void k_finalize(const float* __restrict__ conv_w,
                           const float* __restrict__ bn_gamma,
                           const float* __restrict__ bn_beta)
{
    __shared__ float S[NRED];
    int t = threadIdx.x;
    if (t < NRED) {
        float s = 0.f;
        for (int bl = 0; bl < NBLK_MOM; bl++) s += g_part[bl][t];
        S[t] = s * (1.f / (12.f * (float)BATCH));
    }
    __syncthreads();
    if (t < NCH) {
        float w[16];
#pragma unroll
        for (int i = 0; i < 16; i++) w[i] = conv_w[t * 16 + i];
        float mraw = 0.f;
#pragma unroll
        for (int i = 0; i < 16; i++) mraw += w[i] * S[i];
        float q = 0.f;
        int idx = 16;
#pragma unroll
        for (int k = 0; k < 16; k++)
#pragma unroll
            for (int l = k; l < 16; l++) {
                float coef = (k == l) ? (w[k] * w[l]) : (2.f * w[k] * w[l]);
                q += coef * S[idx];
                idx++;
            }
        float var = q - mraw * mraw;
        float a = bn_gamma[t] * rsqrtf(var + EPSV);
#pragma unroll
        for (int i = 0; i < 16; i++) g_wscaled[t * 16 + i] = a * w[i];
        g_shift[t] = bn_beta[t] - a * mraw;
    }
}

// =========================================================================
// K_prep: W1 -> [k'][n] fp16 (hi only).  kp = p*256+c, f = c*12+p.
// =========================================================================
__global__ void k_prep(const float* __restrict__ pw1, const float* __restrict__ vw1)
{
    int kp = blockIdx.x;
    int n  = threadIdx.x;
    int p = kp >> 8, c = kp & 255;
    int f = c * 12 + p;
    float v = (n < 64) ? pw1[(size_t)f * 64 + n] : vw1[(size_t)f * 64 + (n - 64)];
    g_w1hi[(size_t)kp * 128 + n] = __float2half_rn(v);
}

// =========================================================================
// K4: register-dataflow fused kernel, batched LDSM, 1-term fp16 conv.
// Warp owns m16 x n128. Per iter (K=64): conv 8 HMMA -> fc1 64 HMMA.
// Smem: B ring 3x16384 @0 | Wc hi @49152 | shift @57344
//       epilogue reuse: h1 [128][129] f32 @0, h2 [128][65] @66560
// =========================================================================
#define NITER    48
#define OFF_B    0
#define OFF_WC   49152
#define OFF_SH   57344
#define SMEM_DYN 99840

__global__ __launch_bounds__(256, 2) void k_fused(
    const float* __restrict__ x,
    const float* __restrict__ pb1, const float* __restrict__ vb1,
    const float* __restrict__ pw2, const float* __restrict__ pb2,
    const float* __restrict__ pw3, const float* __restrict__ pb3,
    const float* __restrict__ vw2, const float* __restrict__ vb2,
    const float* __restrict__ vw3, const float* __restrict__ vb3,
    float* __restrict__ out)
{
    extern __shared__ char dyn_pool[];
    __shared__ float biasS[128];

    char* poolA = dyn_pool;
    const uint32_t pool_u = smem_u32(poolA);

    const int tid  = threadIdx.x;
    const int wid  = tid >> 5;
    const int lane = tid & 31;
    const int m0   = blockIdx.x * 128;

    float* shiftS = (float*)(poolA + OFF_SH);

    // ---- one-time smem fills ----
    if (tid < 64)       biasS[tid] = pb1[tid];
    else if (tid < 128) biasS[tid] = vb1[tid - 64];
    {   // folded conv weights -> Wc[k][c] fp16 (hi), swizzled rows of 512B
#pragma unroll
        for (int i = 0; i < 16; i++) {
            int idx = tid + i * 256;
            int k = idx >> 8, c = idx & 255;
            float v = g_wscaled[c * 16 + k];
            uint32_t o = (uint32_t)k * 512 + ((((uint32_t)(c >> 3)) ^ (k & 7)) << 4) + (c & 7) * 2;
            *(__half*)(poolA + OFF_WC + o) = __float2half_rn(v);
        }
    }
    shiftS[tid] = g_shift[tid];

    // ---- fc1 B cp.async lanes ----
    const int brow = tid >> 2;
    const int bq   = (tid & 3) * 4;
    const __half* gB = g_w1hi + (size_t)brow * 128 + bq * 8;
    uint32_t oBs[4];
#pragma unroll
    for (int j = 0; j < 4; j++)
        oBs[j] = (uint32_t)brow * 256 + ((((uint32_t)(bq + j)) ^ (brow & 7)) << 4);

    // ---- prologue B(0), B(1) ----
#pragma unroll
    for (int pc = 0; pc < 2; pc++) {
        const uint32_t sb = pool_u + OFF_B + pc * 16384;
        const size_t kofs = (size_t)pc * 64 * 128;
#pragma unroll
        for (int j = 0; j < 4; j++)
            CP_ASYNC16(sb + oBs[j], gB + kofs + j * 8);
        CP_COMMIT();
    }

    // ---- lane constants ----
    const int g    = lane >> 2;
    const int t2   = (lane & 3) * 2;
    const int b_kl = ((lane >> 3) & 1) * 8 + (lane & 7);
    const int b_ng = (lane >> 4);
    const uint32_t key = (uint32_t)(b_kl & 7);

    // constant per-lane swizzle offsets for fc1 B ldsm (np = 0..7)
    uint32_t offnp[8];
#pragma unroll
    for (int np = 0; np < 8; np++)
        offnp[np] = ((((uint32_t)(np * 2 + b_ng)) ^ key) << 4);

    // D accumulators: m16 x n128 per warp
    float d[16][4];
#pragma unroll
    for (int nt = 0; nt < 16; nt++)
#pragma unroll
        for (int q = 0; q < 4; q++) d[nt][q] = 0.f;

    __syncthreads();   // Wc / shift visible

    // x-fragment registers (fp16 hi only)
    uint32_t xhi[4];
    {
        const float* xb = x + (size_t)(m0 + wid * 16) * 42;
        int o0 = ((t2 >> 2) * 7 + (t2 & 3));
        int k1 = t2 + 8;
        int o1 = ((k1 >> 2) * 7 + (k1 & 3));
        xhi[0] = f2h2(xb[(size_t)g * 42 + o0],       xb[(size_t)g * 42 + o0 + 1]);
        xhi[1] = f2h2(xb[(size_t)(g + 8) * 42 + o0], xb[(size_t)(g + 8) * 42 + o0 + 1]);
        xhi[2] = f2h2(xb[(size_t)g * 42 + o1],       xb[(size_t)g * 42 + o1 + 1]);
        xhi[3] = f2h2(xb[(size_t)(g + 8) * 42 + o1], xb[(size_t)(g + 8) * 42 + o1 + 1]);
    }

    // ================= main loop =================
#pragma unroll 1
    for (int it = 0; it < NITER; it++) {
        CP_WAIT1();
        __syncthreads();   // B[it%3] arrived & visible

        if (it + 2 < NITER) {
            const uint32_t sb = pool_u + OFF_B + ((it + 2) % 3) * 16384;
            const size_t kofs = (size_t)(it + 2) * 64 * 128;
#pragma unroll
            for (int j = 0; j < 4; j++)
                CP_ASYNC16(sb + oBs[j], gB + kofs + j * 8);
        }
        CP_COMMIT();

        if (it > 0 && (it & 3) == 0) {
            const int p = it >> 2;
            const float* xb = x + (size_t)(m0 + wid * 16) * 42 + (p >> 2) * 7 + (p & 3);
            int o0 = ((t2 >> 2) * 7 + (t2 & 3));
            int k1 = t2 + 8;
            int o1 = ((k1 >> 2) * 7 + (k1 & 3));
            xhi[0] = f2h2(xb[(size_t)g * 42 + o0],       xb[(size_t)g * 42 + o0 + 1]);
            xhi[1] = f2h2(xb[(size_t)(g + 8) * 42 + o0], xb[(size_t)(g + 8) * 42 + o0 + 1]);
            xhi[2] = f2h2(xb[(size_t)g * 42 + o1],       xb[(size_t)g * 42 + o1 + 1]);
            xhi[3] = f2h2(xb[(size_t)(g + 8) * 42 + o1], xb[(size_t)(g + 8) * 42 + o1 + 1]);
        }

        const uint32_t sbB = pool_u + OFF_B + (it % 3) * 16384;

#pragma unroll
        for (int gg = 0; gg < 2; gg++) {
            const int grp = (it & 3) * 2 + gg;
            const int bg  = grp * 4;

            // ---- conv: batched W loads, then 4 independent MMAs ----
            uint32_t w0[4], w1[4];
            {
                uint32_t wo0 = (uint32_t)b_kl * 512 + ((((uint32_t)(bg + b_ng)) ^ key) << 4);
                uint32_t wo1 = (uint32_t)b_kl * 512 + ((((uint32_t)(bg + 2 + b_ng)) ^ key) << 4);
                ldsm_x4t(w0, pool_u + OFF_WC + wo0);
                ldsm_x4t(w1, pool_u + OFF_WC + wo1);
            }
            float cd[4][4];
#pragma unroll
            for (int nt = 0; nt < 4; nt++)
#pragma unroll
                for (int q = 0; q < 4; q++) cd[nt][q] = 0.f;
            mma16816(cd[0][0], cd[0][1], cd[0][2], cd[0][3],
                     xhi[0], xhi[1], xhi[2], xhi[3], w0[0], w0[1]);
            mma16816(cd[1][0], cd[1][1], cd[1][2], cd[1][3],
                     xhi[0], xhi[1], xhi[2], xhi[3], w0[2], w0[3]);
            mma16816(cd[2][0], cd[2][1], cd[2][2], cd[2][3],
                     xhi[0], xhi[1], xhi[2], xhi[3], w1[0], w1[1]);
            mma16816(cd[3][0], cd[3][1], cd[3][2], cd[3][3],
                     xhi[0], xhi[1], xhi[2], xhi[3], w1[2], w1[3]);

            // ---- pack: shift + ReLU + fp16 -> 2 A-fragments ----
            uint32_t afr[2][4];
#pragma unroll
            for (int pr = 0; pr < 2; pr++) {
                const float* t0 = cd[pr * 2];
                const float* t1 = cd[pr * 2 + 1];
                float2 s0 = *(const float2*)&shiftS[grp * 32 + pr * 16 + t2];
                float2 s1 = *(const float2*)&shiftS[grp * 32 + pr * 16 + 8 + t2];
                afr[pr][0] = f2h2(fmaxf(t0[0] + s0.x, 0.f), fmaxf(t0[1] + s0.y, 0.f));
                afr[pr][1] = f2h2(fmaxf(t0[2] + s0.x, 0.f), fmaxf(t0[3] + s0.y, 0.f));
                afr[pr][2] = f2h2(fmaxf(t1[0] + s1.x, 0.f), fmaxf(t1[1] + s1.y, 0.f));
                afr[pr][3] = f2h2(fmaxf(t1[2] + s1.x, 0.f), fmaxf(t1[3] + s1.y, 0.f));
            }

            // ---- fc1: 2 k16 chunks; per chunk 2 half-batches (4 ldsm + 8 mma) ----
#pragma unroll
            for (int pr = 0; pr < 2; pr++) {
                const uint32_t* af = afr[pr];
                const uint32_t kbase = sbB + (uint32_t)((gg * 2 + pr) * 16 + b_kl) * 256;
#pragma unroll
                for (int h = 0; h < 2; h++) {
                    uint32_t b4[4][4];
                    ldsm_x4t(b4[0], kbase + offnp[h * 4 + 0]);
                    ldsm_x4t(b4[1], kbase + offnp[h * 4 + 1]);
                    ldsm_x4t(b4[2], kbase + offnp[h * 4 + 2]);
                    ldsm_x4t(b4[3], kbase + offnp[h * 4 + 3]);
#pragma unroll
                    for (int j = 0; j < 4; j++) {
                        const int np = h * 4 + j;
                        mma16816(d[np * 2][0], d[np * 2][1], d[np * 2][2], d[np * 2][3],
                                 af[0], af[1], af[2], af[3], b4[j][0], b4[j][1]);
                        mma16816(d[np * 2 + 1][0], d[np * 2 + 1][1],
                                 d[np * 2 + 1][2], d[np * 2 + 1][3],
                                 af[0], af[1], af[2], af[3], b4[j][2], b4[j][3]);
                    }
                }
            }
        }
    }

    CP_WAIT0();
    __syncthreads();

    // ---------------- epilogue ----------------
    float* h1 = (float*)poolA;              // [128][129]
    float* h2 = (float*)(poolA + 66560);    // [128][65]

    {
        const int m = wid * 16 + g;
#pragma unroll
        for (int nt = 0; nt < 16; nt++) {
            int n = nt * 8 + t2;
            h1[m * 129 + n]           = fmaxf(d[nt][0] + biasS[n], 0.f);
            h1[m * 129 + n + 1]       = fmaxf(d[nt][1] + biasS[n + 1], 0.f);
            h1[(m + 8) * 129 + n]     = fmaxf(d[nt][2] + biasS[n], 0.f);
            h1[(m + 8) * 129 + n + 1] = fmaxf(d[nt][3] + biasS[n + 1], 0.f);
        }
    }
    __syncthreads();

    // layer2
#pragma unroll 1
    for (int it = 0; it < 32; it++) {
        int idx = it * 256 + tid;
        int bd = idx >> 6, o = idx & 63;
        int oo = o & 31;
        const float* h1b  = h1 + bd * 129 + ((o < 32) ? 0 : 64);
        const float* wmat = (o < 32) ? pw2 : vw2;
        float s = (o < 32) ? pb2[oo] : vb2[oo];
#pragma unroll 8
        for (int k = 0; k < 64; k++) s += h1b[k] * wmat[k * 32 + oo];
        h2[bd * 65 + o] = fmaxf(s, 0.f);
    }
    __syncthreads();

    // layer3 + softmax / tanh
    if (tid < 128) {
        int gb = m0 + tid;
        const float* hp = h2 + tid * 65;
        float lg[7];
#pragma unroll
        for (int j = 0; j < 7; j++) {
            float s = pb3[j];
#pragma unroll
            for (int k = 0; k < 32; k++) s += hp[k] * pw3[k * 7 + j];
            lg[j] = s;
        }
        float mx = lg[0];
#pragma unroll
        for (int j = 1; j < 7; j++) mx = fmaxf(mx, lg[j]);
        float se = 0.f;
#pragma unroll
        for (int j = 0; j < 7; j++) { lg[j] = expf(lg[j] - mx); se += lg[j]; }
        float inv = 1.f / se;
#pragma unroll
        for (int j = 0; j < 7; j++) out[(size_t)gb * 7 + j] = lg[j] * inv;

        float v = vb3[0];
#pragma unroll
        for (int k = 0; k < 32; k++) v += hp[32 + k] * vw3[k];
        out[(size_t)BATCH * 7 + gb] = tanhf(v);
    }
}

// =========================================================================
extern "C" void kernel_launch(void* const* d_in, const int* in_sizes, int n_in,
                              void* d_out, int out_size)
{
    const float* x        = (const float*)d_in[0];
    const float* conv_w   = (const float*)d_in[1];
    /* conv_b cancels through batch-norm */
    const float* bn_gamma = (const float*)d_in[3];
    const float* bn_beta  = (const float*)d_in[4];
    const float* pw1 = (const float*)d_in[5];
    const float* pb1 = (const float*)d_in[6];
    const float* pw2 = (const float*)d_in[7];
    const float* pb2 = (const float*)d_in[8];
    const float* pw3 = (const float*)d_in[9];
    const float* pb3 = (const float*)d_in[10];
    const float* vw1 = (const float*)d_in[11];
    const float* vb1 = (const float*)d_in[12];
    const float* vw2 = (const float*)d_in[13];
    const float* vb2 = (const float*)d_in[14];
    const float* vw3 = (const float*)d_in[15];
    const float* vb3 = (const float*)d_in[16];
    float* out = (float*)d_out;

    cudaFuncSetAttribute(k_fused, cudaFuncAttributeMaxDynamicSharedMemorySize, SMEM_DYN);

    k_moments<<<NBLK_MOM, 256>>>(x);
    k_finalize<<<1, 256>>>(conv_w, bn_gamma, bn_beta);
    k_prep<<<FLAT, 128>>>(pw1, vw1);
    k_fused<<<BATCH / 128, 256, SMEM_DYN>>>(x, pb1, vb1, pw2, pb2, pw3, pb3,
                                            vw2, vb2, vw3, vb3, out);
}